// round 8
// baseline (speedup 1.0000x reference)
#include <cuda_runtime.h>
#include <cuda_fp16.h>
#include <cstdint>

// ======================= problem constants =======================
#define DIMX     64
#define HIDX     256
#define NSTEPS   32
#define MTILE    256          // rows per CTA (8 warps x 32 rows)
#define NTHREADS 256

// ======================= SMEM layout (bytes) =====================
#define SM_B1   0
#define SM_TW1  1024
#define SM_B2   2048
#define SM_DB3  3072          // dt * b3 (fp32, 64)
#define SM_W1   4096          // 256n x 64k f16, 128B rows, SW128     (32768 B)
#define SM_W2   36864         // 4 k-chunks x (256n x 64k)            (131072 B)
#define SM_W3   167936        // 4 k-chunks x (64n x 64k), PRE-SCALED BY dt (32768 B)
#define SMEM_BYTES 200704

#define SWZ(off) ((off) ^ (((off) >> 3) & 0x70))

// ======================= device helpers ==========================
__device__ __forceinline__ uint32_t smem_to_u32(const void* p) {
    uint32_t a;
    asm("{ .reg .u64 t; cvta.to.shared.u64 t, %1; cvt.u32.u64 %0, t; }" : "=r"(a) : "l"(p));
    return a;
}
__device__ __forceinline__ uint32_t pack_f16x2(float lo, float hi) {
    uint32_t r;
    asm("cvt.rn.f16x2.f32 %0, %1, %2;" : "=r"(r) : "f"(hi), "f"(lo));
    return r;
}
// SIMD silu on 2 fp32 accumulators -> packed f16x2 A-fragment word.
// silu(a) = a * (0.5*tanh(0.5a) + 0.5): 1 cvt + 2 HMUL2 + 1 MUFU + 1 HFMA2.
__device__ __forceinline__ uint32_t silu2(float lo, float hi, uint32_t h05) {
    uint32_t ah = pack_f16x2(lo, hi), t, s, h;
    asm("mul.rn.f16x2 %0, %1, %2;"     : "=r"(t) : "r"(ah), "r"(h05));
    asm("tanh.approx.f16x2 %0, %1;"    : "=r"(t) : "r"(t));
    asm("fma.rn.f16x2 %0, %1, %2, %2;" : "=r"(s) : "r"(t), "r"(h05));
    asm("mul.rn.f16x2 %0, %1, %2;"     : "=r"(h) : "r"(ah), "r"(s));
    return h;
}
__device__ __forceinline__ void ldsm4(uint32_t& r0, uint32_t& r1, uint32_t& r2, uint32_t& r3,
                                      uint32_t addr) {
    asm volatile("ldmatrix.sync.aligned.m8n8.x4.shared.b16 {%0,%1,%2,%3}, [%4];"
                 : "=r"(r0), "=r"(r1), "=r"(r2), "=r"(r3) : "r"(addr));
}
__device__ __forceinline__ void mma_f16(float* c, const uint32_t* a, uint32_t b0, uint32_t b1) {
    asm volatile("mma.sync.aligned.m16n8k16.row.col.f32.f16.f16.f32 "
                 "{%0,%1,%2,%3}, {%4,%5,%6,%7}, {%8,%9}, {%0,%1,%2,%3};"
                 : "+f"(c[0]), "+f"(c[1]), "+f"(c[2]), "+f"(c[3])
                 : "r"(a[0]), "r"(a[1]), "r"(a[2]), "r"(a[3]), "r"(b0), "r"(b1));
}

// ======================= kernel ==================================
__global__ void __launch_bounds__(NTHREADS, 1) flow_kernel(
    const float* __restrict__ x0, const float* __restrict__ W1,
    const float* __restrict__ b1, const float* __restrict__ W2,
    const float* __restrict__ b2, const float* __restrict__ W3,
    const float* __restrict__ b3, float* __restrict__ out)
{
    extern __shared__ char smem[];
    const uint32_t sbase = smem_to_u32(smem);
    const int tid  = threadIdx.x;
    const int wid  = tid >> 5;
    const int lane = tid & 31;

    float* sb1  = (float*)(smem + SM_B1);
    float* stw1 = (float*)(smem + SM_TW1);
    float* sb2  = (float*)(smem + SM_B2);
    float* sdb3 = (float*)(smem + SM_DB3);

    const float dt = 1.0f / NSTEPS;
    const uint32_t h05 = 0x38003800u;   // (0.5, 0.5) f16x2

    // ---------------- prologue: biases ----------------
    for (int i = tid; i < HIDX; i += NTHREADS) {
        sb1[i]  = b1[i];
        stw1[i] = W1[DIMX * HIDX + i];   // t-row of W1
        sb2[i]  = b2[i];
    }
    if (tid < DIMX) sdb3[tid] = dt * b3[tid];

    // ---------------- prologue: weights -> f16, W^T layout (n rows, k contig), SW128 ----
    for (int idx = tid; idx < DIMX * HIDX; idx += NTHREADS) {          // W1 (64k,256n)
        int k = idx >> 8, n = idx & 255;
        uint32_t off = (uint32_t)(n * 128 + k * 2);
        *(__half*)(smem + SM_W1 + SWZ(off)) = __float2half(W1[idx]);
    }
    for (int idx = tid; idx < HIDX * HIDX; idx += NTHREADS) {          // W2 (256k,256n)
        int k = idx >> 8, n = idx & 255;
        int c = k >> 6, kk = k & 63;
        uint32_t off = (uint32_t)(n * 128 + kk * 2);
        *(__half*)(smem + SM_W2 + c * 32768 + SWZ(off)) = __float2half(W2[idx]);
    }
    for (int idx = tid; idx < HIDX * DIMX; idx += NTHREADS) {          // W3 (256k,64n), x dt
        int k = idx >> 6, n = idx & 63;
        int c = k >> 6, kk = k & 63;
        uint32_t off = (uint32_t)(n * 128 + kk * 2);
        *(__half*)(smem + SM_W3 + c * 8192 + SWZ(off)) = __float2half(dt * W3[idx]);
    }
    __syncthreads();

    // ---------------- per-lane ldmatrix addressing ----------------
    const int r = lane & 7, g = lane >> 3;
    const uint32_t ld_row = (uint32_t)((r + ((g >> 1) << 3)) * 128);
    const uint32_t g1 = (uint32_t)(g & 1);
    #define KOFF(kt) ((((uint32_t)(((kt) << 1) | g1) ^ (uint32_t)r) << 4))

    // ---------------- load x: m32 per warp, fp32 C-fragment layout ----------------
    const long rowBase = (long)blockIdx.x * MTILE + wid * 32 + (lane >> 2);
    const int  q2 = (lane & 3) * 2;

    float x[64];
    #pragma unroll
    for (int mt = 0; mt < 2; mt++) {
        const float* pA = x0 + (rowBase + mt * 16) * DIMX;
        const float* pB = x0 + (rowBase + mt * 16 + 8) * DIMX;
        #pragma unroll
        for (int nt = 0; nt < 8; nt++) {
            float2 a = *(const float2*)(pA + nt * 8 + q2);
            float2 b = *(const float2*)(pB + nt * 8 + q2);
            x[(mt * 8 + nt) * 4 + 0] = a.x; x[(mt * 8 + nt) * 4 + 1] = a.y;
            x[(mt * 8 + nt) * 4 + 2] = b.x; x[(mt * 8 + nt) * 4 + 3] = b.y;
        }
    }

    uint32_t hA[128];   // GEMM2 A fragments (f16x2): [(kt*2+mt)*4 + j], kt=0..15

    #pragma unroll 1
    for (int s = 0; s < NSTEPS; s++) {
        const float tval = ((float)s + 0.5f) * dt;

        // ---- x -> f16 A fragments for GEMM1: xA[(kt*2+mt)*4+j], kt=0..3 ----
        uint32_t xA[32];
        #pragma unroll
        for (int kt = 0; kt < 4; kt++) {
            #pragma unroll
            for (int mt = 0; mt < 2; mt++) {
                const float* xs = x + (mt * 8 + 2 * kt) * 4;
                uint32_t* a = xA + (kt * 2 + mt) * 4;
                a[0] = pack_f16x2(xs[0], xs[1]);
                a[1] = pack_f16x2(xs[2], xs[3]);
                a[2] = pack_f16x2(xs[4], xs[5]);
                a[3] = pack_f16x2(xs[6], xs[7]);
            }
        }

        // ======== GEMM1: h = silu(x@W1 + b1 + t*tw1)  (M=32/warp, N=256, K=64) ======
        // Accumulators initialized with the bias (no epilogue adds).
        #pragma unroll
        for (int pair = 0; pair < 16; pair++) {
            const int col0 = pair * 16 + q2;
            float2 bA = *(const float2*)(sb1 + col0);
            float2 tA = *(const float2*)(stw1 + col0);
            float2 bB = *(const float2*)(sb1 + col0 + 8);
            float2 tB = *(const float2*)(stw1 + col0 + 8);
            const float bAx = fmaf(tval, tA.x, bA.x), bAy = fmaf(tval, tA.y, bA.y);
            const float bBx = fmaf(tval, tB.x, bB.x), bBy = fmaf(tval, tB.y, bB.y);
            float C[16];
            #pragma unroll
            for (int mt = 0; mt < 2; mt++) {
                C[mt * 8 + 0] = bAx; C[mt * 8 + 1] = bAy;
                C[mt * 8 + 2] = bAx; C[mt * 8 + 3] = bAy;
                C[mt * 8 + 4] = bBx; C[mt * 8 + 5] = bBy;
                C[mt * 8 + 6] = bBx; C[mt * 8 + 7] = bBy;
            }
            const uint32_t base = sbase + SM_W1 + (uint32_t)(pair * 2048) + ld_row;
            #pragma unroll
            for (int kt = 0; kt < 4; kt++) {
                uint32_t w0, w1_, w2_, w3_;
                ldsm4(w0, w1_, w2_, w3_, base + KOFF(kt));
                mma_f16(C + 0,  xA + (kt * 2 + 0) * 4, w0,  w1_);
                mma_f16(C + 4,  xA + (kt * 2 + 0) * 4, w2_, w3_);
                mma_f16(C + 8,  xA + (kt * 2 + 1) * 4, w0,  w1_);
                mma_f16(C + 12, xA + (kt * 2 + 1) * 4, w2_, w3_);
            }
            #pragma unroll
            for (int mt = 0; mt < 2; mt++) {
                const float* c = C + mt * 8;
                uint32_t* h = hA + (pair * 2 + mt) * 4;
                h[0] = silu2(c[0], c[1], h05);
                h[1] = silu2(c[2], c[3], h05);
                h[2] = silu2(c[4], c[5], h05);
                h[3] = silu2(c[6], c[7], h05);
            }
        }

        // ==== GEMM2 (N=256,K=256) fused with GEMM3 (N=64,K=256), chunk = 32 cols ====
        // 8 independent chains; accumulators init with b2; W3 carries dt; GEMM3
        // accumulates straight into fp32 x.
        #pragma unroll 1
        for (int ch = 0; ch < 8; ch++) {
            float C2[32];
            #pragma unroll
            for (int p = 0; p < 2; p++) {
                const int col0 = ch * 32 + p * 16 + q2;
                float2 bA = *(const float2*)(sb2 + col0);
                float2 bB = *(const float2*)(sb2 + col0 + 8);
                #pragma unroll
                for (int mt = 0; mt < 2; mt++) {
                    float* c = C2 + p * 16 + mt * 8;
                    c[0] = bA.x; c[1] = bA.y; c[2] = bA.x; c[3] = bA.y;
                    c[4] = bB.x; c[5] = bB.y; c[6] = bB.x; c[7] = bB.y;
                }
            }

            const uint32_t w2base = sbase + SM_W2 + (uint32_t)(ch * 4096) + ld_row;
            #pragma unroll
            for (int kt = 0; kt < 16; kt++) {
                const uint32_t koff = (uint32_t)((kt >> 2) * 32768) + KOFF(kt & 3);
                const uint32_t* a0 = hA + (kt * 2 + 0) * 4;
                const uint32_t* a1 = hA + (kt * 2 + 1) * 4;
                #pragma unroll
                for (int p = 0; p < 2; p++) {
                    uint32_t w0, w1_, w2_, w3_;
                    ldsm4(w0, w1_, w2_, w3_, w2base + (uint32_t)(p * 2048) + koff);
                    mma_f16(C2 + p * 16 + 0,  a0, w0,  w1_);
                    mma_f16(C2 + p * 16 + 4,  a0, w2_, w3_);
                    mma_f16(C2 + p * 16 + 8,  a1, w0,  w1_);
                    mma_f16(C2 + p * 16 + 12, a1, w2_, w3_);
                }
            }

            // ---- epilogue: gA = f16x2(silu(C2)) (bias already inside) ----
            uint32_t gA[16];
            #pragma unroll
            for (int p = 0; p < 2; p++) {
                #pragma unroll
                for (int mt = 0; mt < 2; mt++) {
                    const float* c = C2 + p * 16 + mt * 8;
                    uint32_t* ga = gA + (p * 2 + mt) * 4;
                    ga[0] = silu2(c[0], c[1], h05);
                    ga[1] = silu2(c[2], c[3], h05);
                    ga[2] = silu2(c[4], c[5], h05);
                    ga[3] = silu2(c[6], c[7], h05);
                }
            }

            // ---- GEMM3 k-slices: x += gA @ (dt*W3)[k = ch*32 .. +31] ----
            #pragma unroll
            for (int p = 0; p < 2; p++) {
                const int kt3 = ch * 2 + p;
                const uint32_t w3base = sbase + SM_W3 + (uint32_t)((kt3 >> 2) * 8192) + ld_row;
                const uint32_t k3off = KOFF(kt3 & 3);
                #pragma unroll
                for (int ntp = 0; ntp < 4; ntp++) {
                    uint32_t w0, w1_, w2_, w3_;
                    ldsm4(w0, w1_, w2_, w3_, w3base + (uint32_t)(ntp * 2048) + k3off);
                    mma_f16(x + (0 * 8 + 2 * ntp) * 4,     gA + (p * 2 + 0) * 4, w0,  w1_);
                    mma_f16(x + (0 * 8 + 2 * ntp + 1) * 4, gA + (p * 2 + 0) * 4, w2_, w3_);
                    mma_f16(x + (1 * 8 + 2 * ntp) * 4,     gA + (p * 2 + 1) * 4, w0,  w1_);
                    mma_f16(x + (1 * 8 + 2 * ntp + 1) * 4, gA + (p * 2 + 1) * 4, w2_, w3_);
                }
            }
        }

        // ---- x += dt * b3 (linear contribution) ----
        #pragma unroll
        for (int nt = 0; nt < 8; nt++) {
            float2 p = *(const float2*)(sdb3 + nt * 8 + q2);
            #pragma unroll
            for (int mt = 0; mt < 2; mt++) {
                float* xs = x + (mt * 8 + nt) * 4;
                xs[0] += p.x; xs[1] += p.y; xs[2] += p.x; xs[3] += p.y;
            }
        }
    }

    // ---------------- store result ----------------
    #pragma unroll
    for (int mt = 0; mt < 2; mt++) {
        float* pA = out + (rowBase + mt * 16) * DIMX;
        float* pB = out + (rowBase + mt * 16 + 8) * DIMX;
        #pragma unroll
        for (int nt = 0; nt < 8; nt++) {
            const float* xs = x + (mt * 8 + nt) * 4;
            *(float2*)(pA + nt * 8 + q2) = make_float2(xs[0], xs[1]);
            *(float2*)(pB + nt * 8 + q2) = make_float2(xs[2], xs[3]);
        }
    }
}

// ======================= launch ==================================
extern "C" void kernel_launch(void* const* d_in, const int* in_sizes, int n_in,
                              void* d_out, int out_size) {
    const float* x0 = (const float*)d_in[0];
    const float* W1 = (const float*)d_in[1];
    const float* b1 = (const float*)d_in[2];
    const float* W2 = (const float*)d_in[3];
    const float* b2 = (const float*)d_in[4];
    const float* W3 = (const float*)d_in[5];
    const float* b3 = (const float*)d_in[6];
    float* out = (float*)d_out;

    const int nrows = in_sizes[0] / DIMX;
    const int grid  = nrows / MTILE;   // 512

    cudaFuncSetAttribute(flow_kernel, cudaFuncAttributeMaxDynamicSharedMemorySize, SMEM_BYTES);
    flow_kernel<<<grid, NTHREADS, SMEM_BYTES>>>(x0, W1, b1, W2, b2, W3, b3, out);
}

// round 9
// speedup vs baseline: 1.1143x; 1.1143x over previous
#include <cuda_runtime.h>
#include <cuda_fp16.h>
#include <cstdint>

// ======================= problem constants =======================
#define DIMX     64
#define HIDX     256
#define NSTEPS   32
#define MTILE    256          // rows per CTA (8 warps x 32 rows)
#define NTHREADS 256

// ======================= SMEM layout (bytes) =====================
#define SM_B1P  0             // b1 packed f16x2 (128 u32)           (512 B)
#define SM_TW1P 512           // t-row of W1 packed f16x2            (512 B)
#define SM_B2P  1024          // b2 packed f16x2                     (512 B)
#define SM_DB3  3072          // dt * b3 (fp32, 64)
#define SM_W1   4096          // 256n x 64k f16, 128B rows, SW128     (32768 B)
#define SM_W2   36864         // 4 k-chunks x (256n x 64k)            (131072 B)
#define SM_W3   167936        // 4 k-chunks x (64n x 64k), PRE-SCALED BY dt (32768 B)
#define SMEM_BYTES 200704

#define SWZ(off) ((off) ^ (((off) >> 3) & 0x70))

// ======================= device helpers ==========================
__device__ __forceinline__ uint32_t smem_to_u32(const void* p) {
    uint32_t a;
    asm("{ .reg .u64 t; cvta.to.shared.u64 t, %1; cvt.u32.u64 %0, t; }" : "=r"(a) : "l"(p));
    return a;
}
__device__ __forceinline__ uint32_t pack_f16x2(float lo, float hi) {
    uint32_t r;
    asm("cvt.rn.f16x2.f32 %0, %1, %2;" : "=r"(r) : "f"(hi), "f"(lo));
    return r;
}
// SIMD silu directly on packed f16x2: a*(0.5*tanh(0.5a)+0.5) — 4 instr, 1 MUFU.
__device__ __forceinline__ uint32_t silu2h(uint32_t ah, uint32_t h05) {
    uint32_t t, s, h;
    asm("mul.rn.f16x2 %0, %1, %2;"     : "=r"(t) : "r"(ah), "r"(h05));
    asm("tanh.approx.f16x2 %0, %1;"    : "=r"(t) : "r"(t));
    asm("fma.rn.f16x2 %0, %1, %2, %2;" : "=r"(s) : "r"(t), "r"(h05));
    asm("mul.rn.f16x2 %0, %1, %2;"     : "=r"(h) : "r"(ah), "r"(s));
    return h;
}
__device__ __forceinline__ uint32_t hfma2(uint32_t a, uint32_t b, uint32_t c) {
    uint32_t r;
    asm("fma.rn.f16x2 %0, %1, %2, %3;" : "=r"(r) : "r"(a), "r"(b), "r"(c));
    return r;
}
__device__ __forceinline__ void ldsm4(uint32_t& r0, uint32_t& r1, uint32_t& r2, uint32_t& r3,
                                      uint32_t addr) {
    asm volatile("ldmatrix.sync.aligned.m8n8.x4.shared.b16 {%0,%1,%2,%3}, [%4];"
                 : "=r"(r0), "=r"(r1), "=r"(r2), "=r"(r3) : "r"(addr));
}
// f16-accumulate mma: D,C = 2 regs (f16x2 pair: {row, row+8} x cols q2,q2+1)
__device__ __forceinline__ void mma_h(uint32_t* d, const uint32_t* a, uint32_t b0, uint32_t b1) {
    asm volatile("mma.sync.aligned.m16n8k16.row.col.f16.f16.f16.f16 "
                 "{%0,%1}, {%2,%3,%4,%5}, {%6,%7}, {%0,%1};"
                 : "+r"(d[0]), "+r"(d[1])
                 : "r"(a[0]), "r"(a[1]), "r"(a[2]), "r"(a[3]), "r"(b0), "r"(b1));
}
// f32-accumulate mma (GEMM3 -> x)
__device__ __forceinline__ void mma_f(float* c, const uint32_t* a, uint32_t b0, uint32_t b1) {
    asm volatile("mma.sync.aligned.m16n8k16.row.col.f32.f16.f16.f32 "
                 "{%0,%1,%2,%3}, {%4,%5,%6,%7}, {%8,%9}, {%0,%1,%2,%3};"
                 : "+f"(c[0]), "+f"(c[1]), "+f"(c[2]), "+f"(c[3])
                 : "r"(a[0]), "r"(a[1]), "r"(a[2]), "r"(a[3]), "r"(b0), "r"(b1));
}

// ======================= kernel ==================================
__global__ void __launch_bounds__(NTHREADS, 1) flow_kernel(
    const float* __restrict__ x0, const float* __restrict__ W1,
    const float* __restrict__ b1, const float* __restrict__ W2,
    const float* __restrict__ b2, const float* __restrict__ W3,
    const float* __restrict__ b3, float* __restrict__ out)
{
    extern __shared__ char smem[];
    const uint32_t sbase = smem_to_u32(smem);
    const int tid  = threadIdx.x;
    const int wid  = tid >> 5;
    const int lane = tid & 31;

    uint32_t* sb1p  = (uint32_t*)(smem + SM_B1P);
    uint32_t* stw1p = (uint32_t*)(smem + SM_TW1P);
    uint32_t* sb2p  = (uint32_t*)(smem + SM_B2P);
    float*    sdb3  = (float*)(smem + SM_DB3);

    const float dt = 1.0f / NSTEPS;
    const uint32_t h05 = 0x38003800u;   // (0.5, 0.5) f16x2

    // ---------------- prologue: packed biases ----------------
    if (tid < 128) {
        sb1p[tid]  = pack_f16x2(b1[2 * tid], b1[2 * tid + 1]);
        stw1p[tid] = pack_f16x2(W1[DIMX * HIDX + 2 * tid], W1[DIMX * HIDX + 2 * tid + 1]);
        sb2p[tid]  = pack_f16x2(b2[2 * tid], b2[2 * tid + 1]);
    }
    if (tid < DIMX) sdb3[tid] = dt * b3[tid];

    // ---------------- prologue: weights -> f16, W^T layout (n rows, k contig), SW128 ----
    for (int idx = tid; idx < DIMX * HIDX; idx += NTHREADS) {          // W1 (64k,256n)
        int k = idx >> 8, n = idx & 255;
        uint32_t off = (uint32_t)(n * 128 + k * 2);
        *(__half*)(smem + SM_W1 + SWZ(off)) = __float2half(W1[idx]);
    }
    for (int idx = tid; idx < HIDX * HIDX; idx += NTHREADS) {          // W2 (256k,256n)
        int k = idx >> 8, n = idx & 255;
        int c = k >> 6, kk = k & 63;
        uint32_t off = (uint32_t)(n * 128 + kk * 2);
        *(__half*)(smem + SM_W2 + c * 32768 + SWZ(off)) = __float2half(W2[idx]);
    }
    for (int idx = tid; idx < HIDX * DIMX; idx += NTHREADS) {          // W3 (256k,64n), x dt
        int k = idx >> 6, n = idx & 63;
        int c = k >> 6, kk = k & 63;
        uint32_t off = (uint32_t)(n * 128 + kk * 2);
        *(__half*)(smem + SM_W3 + c * 8192 + SWZ(off)) = __float2half(dt * W3[idx]);
    }
    __syncthreads();

    // ---------------- per-lane ldmatrix addressing ----------------
    const int r = lane & 7, g = lane >> 3;
    const uint32_t ld_row = (uint32_t)((r + ((g >> 1) << 3)) * 128);
    const uint32_t g1 = (uint32_t)(g & 1);
    #define KOFF(kt) ((((uint32_t)(((kt) << 1) | g1) ^ (uint32_t)r) << 4))

    // ---------------- load x: m32 per warp, fp32 C-fragment layout ----------------
    const long rowBase = (long)blockIdx.x * MTILE + wid * 32 + (lane >> 2);
    const int  q2 = (lane & 3) * 2;
    const int  l4 = lane & 3;           // packed-bias index within col pair group

    float x[64];
    #pragma unroll
    for (int mt = 0; mt < 2; mt++) {
        const float* pA = x0 + (rowBase + mt * 16) * DIMX;
        const float* pB = x0 + (rowBase + mt * 16 + 8) * DIMX;
        #pragma unroll
        for (int nt = 0; nt < 8; nt++) {
            float2 a = *(const float2*)(pA + nt * 8 + q2);
            float2 b = *(const float2*)(pB + nt * 8 + q2);
            x[(mt * 8 + nt) * 4 + 0] = a.x; x[(mt * 8 + nt) * 4 + 1] = a.y;
            x[(mt * 8 + nt) * 4 + 2] = b.x; x[(mt * 8 + nt) * 4 + 3] = b.y;
        }
    }

    uint32_t hA[128];   // GEMM2 A fragments (f16x2): [(kt*2+mt)*4 + j], kt=0..15

    #pragma unroll 1
    for (int s = 0; s < NSTEPS; s++) {
        const float tvalf = ((float)s + 0.5f) * dt;
        const uint32_t tval2 = pack_f16x2(tvalf, tvalf);

        // ---- x -> f16 A fragments for GEMM1: xA[(kt*2+mt)*4+j], kt=0..3 ----
        uint32_t xA[32];
        #pragma unroll
        for (int kt = 0; kt < 4; kt++) {
            #pragma unroll
            for (int mt = 0; mt < 2; mt++) {
                const float* xs = x + (mt * 8 + 2 * kt) * 4;
                uint32_t* a = xA + (kt * 2 + mt) * 4;
                a[0] = pack_f16x2(xs[0], xs[1]);
                a[1] = pack_f16x2(xs[2], xs[3]);
                a[2] = pack_f16x2(xs[4], xs[5]);
                a[3] = pack_f16x2(xs[6], xs[7]);
            }
        }

        // ======== GEMM1: h = silu(x@W1 + b1 + t*tw1), f16 accum ========
        // C/D = packed f16x2; bias pre-loaded into accumulators; D regs become
        // hA (GEMM2 A-fragments) after in-place SIMD silu.
        #pragma unroll
        for (int pair = 0; pair < 16; pair++) {
            const uint32_t biasA = hfma2(tval2, stw1p[pair * 8 + l4],     sb1p[pair * 8 + l4]);
            const uint32_t biasB = hfma2(tval2, stw1p[pair * 8 + 4 + l4], sb1p[pair * 8 + 4 + l4]);
            uint32_t C[8];   // [mt*4 + {0,1}]=n-half A {d0,d1}; [mt*4 + {2,3}]=n-half B
            #pragma unroll
            for (int mt = 0; mt < 2; mt++) {
                C[mt * 4 + 0] = biasA; C[mt * 4 + 1] = biasA;
                C[mt * 4 + 2] = biasB; C[mt * 4 + 3] = biasB;
            }
            const uint32_t base = sbase + SM_W1 + (uint32_t)(pair * 2048) + ld_row;
            #pragma unroll
            for (int kt = 0; kt < 4; kt++) {
                uint32_t w0, w1_, w2_, w3_;
                ldsm4(w0, w1_, w2_, w3_, base + KOFF(kt));
                mma_h(C + 0, xA + (kt * 2 + 0) * 4, w0,  w1_);
                mma_h(C + 2, xA + (kt * 2 + 0) * 4, w2_, w3_);
                mma_h(C + 4, xA + (kt * 2 + 1) * 4, w0,  w1_);
                mma_h(C + 6, xA + (kt * 2 + 1) * 4, w2_, w3_);
            }
            #pragma unroll
            for (int mt = 0; mt < 2; mt++) {
                uint32_t* h = hA + (pair * 2 + mt) * 4;
                h[0] = silu2h(C[mt * 4 + 0], h05);
                h[1] = silu2h(C[mt * 4 + 1], h05);
                h[2] = silu2h(C[mt * 4 + 2], h05);
                h[3] = silu2h(C[mt * 4 + 3], h05);
            }
        }

        // ==== GEMM2 (f16 accum, N=256,K=256) fused with GEMM3 (f32 accum into x) ====
        // chunk = 32 cols; B fragments double-buffered across kt (regs freed by f16 C).
        #pragma unroll 1
        for (int ch = 0; ch < 8; ch++) {
            // C2h[(nt*2+mt)*2 + {0,1}] : nt=0..3 (8-col tiles), {d0,d1}
            uint32_t C2h[16];
            #pragma unroll
            for (int nt = 0; nt < 4; nt++) {
                const uint32_t b2v = sb2p[ch * 16 + nt * 4 + l4];
                C2h[(nt * 2 + 0) * 2 + 0] = b2v; C2h[(nt * 2 + 0) * 2 + 1] = b2v;
                C2h[(nt * 2 + 1) * 2 + 0] = b2v; C2h[(nt * 2 + 1) * 2 + 1] = b2v;
            }

            const uint32_t w2base = sbase + SM_W2 + (uint32_t)(ch * 4096) + ld_row;
            uint32_t B0[4], B1[4];
            ldsm4(B0[0], B0[1], B0[2], B0[3], w2base + KOFF(0));
            ldsm4(B1[0], B1[1], B1[2], B1[3], w2base + 2048u + KOFF(0));
            #pragma unroll
            for (int kt = 0; kt < 16; kt++) {
                uint32_t N0[4], N1[4];
                if (kt < 15) {
                    const int kn = kt + 1;
                    const uint32_t ko = (uint32_t)((kn >> 2) * 32768) + KOFF(kn & 3);
                    ldsm4(N0[0], N0[1], N0[2], N0[3], w2base + ko);
                    ldsm4(N1[0], N1[1], N1[2], N1[3], w2base + 2048u + ko);
                }
                const uint32_t* a0 = hA + (kt * 2 + 0) * 4;
                const uint32_t* a1 = hA + (kt * 2 + 1) * 4;
                mma_h(C2h + 0,  a0, B0[0], B0[1]);   // nt0 mt0
                mma_h(C2h + 2,  a1, B0[0], B0[1]);   // nt0 mt1
                mma_h(C2h + 4,  a0, B0[2], B0[3]);   // nt1 mt0
                mma_h(C2h + 6,  a1, B0[2], B0[3]);   // nt1 mt1
                mma_h(C2h + 8,  a0, B1[0], B1[1]);   // nt2 mt0
                mma_h(C2h + 10, a1, B1[0], B1[1]);   // nt2 mt1
                mma_h(C2h + 12, a0, B1[2], B1[3]);   // nt3 mt0
                mma_h(C2h + 14, a1, B1[2], B1[3]);   // nt3 mt1
                if (kt < 15) {
                    #pragma unroll
                    for (int j = 0; j < 4; j++) { B0[j] = N0[j]; B1[j] = N1[j]; }
                }
            }

            // ---- epilogue: in-place SIMD silu -> GEMM3 A fragments ----
            #pragma unroll
            for (int i = 0; i < 16; i++) C2h[i] = silu2h(C2h[i], h05);

            // ---- GEMM3 k-slices: x += silu(C2) @ (dt*W3)[k = ch*32 .. +31] ----
            // A-frag for kt3=ch*2+p, mt: {C2h[nt=2p,mt], C2h[nt=2p+1,mt]}
            #pragma unroll
            for (int p = 0; p < 2; p++) {
                uint32_t a0[4] = { C2h[((2*p)*2+0)*2+0], C2h[((2*p)*2+0)*2+1],
                                   C2h[((2*p+1)*2+0)*2+0], C2h[((2*p+1)*2+0)*2+1] };
                uint32_t a1[4] = { C2h[((2*p)*2+1)*2+0], C2h[((2*p)*2+1)*2+1],
                                   C2h[((2*p+1)*2+1)*2+0], C2h[((2*p+1)*2+1)*2+1] };
                const int kt3 = ch * 2 + p;
                const uint32_t w3base = sbase + SM_W3 + (uint32_t)((kt3 >> 2) * 8192) + ld_row;
                const uint32_t k3off = KOFF(kt3 & 3);
                #pragma unroll
                for (int ntp = 0; ntp < 4; ntp++) {
                    uint32_t w0, w1_, w2_, w3_;
                    ldsm4(w0, w1_, w2_, w3_, w3base + (uint32_t)(ntp * 2048) + k3off);
                    mma_f(x + (0 * 8 + 2 * ntp) * 4,     a0, w0,  w1_);
                    mma_f(x + (0 * 8 + 2 * ntp + 1) * 4, a0, w2_, w3_);
                    mma_f(x + (1 * 8 + 2 * ntp) * 4,     a1, w0,  w1_);
                    mma_f(x + (1 * 8 + 2 * ntp + 1) * 4, a1, w2_, w3_);
                }
            }
        }

        // ---- x += dt * b3 (linear contribution) ----
        #pragma unroll
        for (int nt = 0; nt < 8; nt++) {
            float2 p = *(const float2*)(sdb3 + nt * 8 + q2);
            #pragma unroll
            for (int mt = 0; mt < 2; mt++) {
                float* xs = x + (mt * 8 + nt) * 4;
                xs[0] += p.x; xs[1] += p.y; xs[2] += p.x; xs[3] += p.y;
            }
        }
    }

    // ---------------- store result ----------------
    #pragma unroll
    for (int mt = 0; mt < 2; mt++) {
        float* pA = out + (rowBase + mt * 16) * DIMX;
        float* pB = out + (rowBase + mt * 16 + 8) * DIMX;
        #pragma unroll
        for (int nt = 0; nt < 8; nt++) {
            const float* xs = x + (mt * 8 + nt) * 4;
            *(float2*)(pA + nt * 8 + q2) = make_float2(xs[0], xs[1]);
            *(float2*)(pB + nt * 8 + q2) = make_float2(xs[2], xs[3]);
        }
    }
}

// ======================= launch ==================================
extern "C" void kernel_launch(void* const* d_in, const int* in_sizes, int n_in,
                              void* d_out, int out_size) {
    const float* x0 = (const float*)d_in[0];
    const float* W1 = (const float*)d_in[1];
    const float* b1 = (const float*)d_in[2];
    const float* W2 = (const float*)d_in[3];
    const float* b2 = (const float*)d_in[4];
    const float* W3 = (const float*)d_in[5];
    const float* b3 = (const float*)d_in[6];
    float* out = (float*)d_out;

    const int nrows = in_sizes[0] / DIMX;
    const int grid  = nrows / MTILE;   // 512

    cudaFuncSetAttribute(flow_kernel, cudaFuncAttributeMaxDynamicSharedMemorySize, SMEM_BYTES);
    flow_kernel<<<grid, NTHREADS, SMEM_BYTES>>>(x0, W1, b1, W2, b2, W3, b3, out);
}

// round 10
// speedup vs baseline: 1.2732x; 1.1426x over previous
#include <cuda_runtime.h>
#include <cuda_fp16.h>
#include <cstdint>

// ======================= problem constants =======================
#define DIMX     64
#define HIDX     256
#define NSTEPS   32
#define NTHREADS 256

// two-size grid: 444 big CTAs (256 rows, m32/warp) = 3 full waves,
// then 136 small CTAs (128 rows, m16/warp) backfill the tail.
// 444*256 + 136*128 = 131072.
#define NBIG     444
#define NSMALL   136
#define BIGROWS  (NBIG * 256)

// ======================= SMEM layout (bytes) =====================
#define SM_B1P  0             // b1 packed f16x2 (128 u32)
#define SM_TW1P 512           // t-row of W1 packed f16x2
#define SM_B2P  1024          // b2 packed f16x2
#define SM_DB3  3072          // dt * b3 (fp32, 64)
#define SM_W1   4096          // 256n x 64k f16, 128B rows, SW128     (32768 B)
#define SM_W2   36864         // 4 k-chunks x (256n x 64k)            (131072 B)
#define SM_W3   167936        // 4 k-chunks x (64n x 64k), PRE-SCALED BY dt (32768 B)
#define SMEM_BYTES 200704

#define SWZ(off) ((off) ^ (((off) >> 3) & 0x70))

// ======================= device helpers ==========================
__device__ __forceinline__ uint32_t smem_to_u32(const void* p) {
    uint32_t a;
    asm("{ .reg .u64 t; cvta.to.shared.u64 t, %1; cvt.u32.u64 %0, t; }" : "=r"(a) : "l"(p));
    return a;
}
__device__ __forceinline__ uint32_t pack_f16x2(float lo, float hi) {
    uint32_t r;
    asm("cvt.rn.f16x2.f32 %0, %1, %2;" : "=r"(r) : "f"(hi), "f"(lo));
    return r;
}
__device__ __forceinline__ uint32_t silu2h(uint32_t ah, uint32_t h05) {
    uint32_t t, s, h;
    asm("mul.rn.f16x2 %0, %1, %2;"     : "=r"(t) : "r"(ah), "r"(h05));
    asm("tanh.approx.f16x2 %0, %1;"    : "=r"(t) : "r"(t));
    asm("fma.rn.f16x2 %0, %1, %2, %2;" : "=r"(s) : "r"(t), "r"(h05));
    asm("mul.rn.f16x2 %0, %1, %2;"     : "=r"(h) : "r"(ah), "r"(s));
    return h;
}
__device__ __forceinline__ uint32_t hfma2(uint32_t a, uint32_t b, uint32_t c) {
    uint32_t r;
    asm("fma.rn.f16x2 %0, %1, %2, %3;" : "=r"(r) : "r"(a), "r"(b), "r"(c));
    return r;
}
__device__ __forceinline__ void ldsm4(uint32_t& r0, uint32_t& r1, uint32_t& r2, uint32_t& r3,
                                      uint32_t addr) {
    asm volatile("ldmatrix.sync.aligned.m8n8.x4.shared.b16 {%0,%1,%2,%3}, [%4];"
                 : "=r"(r0), "=r"(r1), "=r"(r2), "=r"(r3) : "r"(addr));
}
__device__ __forceinline__ void mma_h(uint32_t* d, const uint32_t* a, uint32_t b0, uint32_t b1) {
    asm volatile("mma.sync.aligned.m16n8k16.row.col.f16.f16.f16.f16 "
                 "{%0,%1}, {%2,%3,%4,%5}, {%6,%7}, {%0,%1};"
                 : "+r"(d[0]), "+r"(d[1])
                 : "r"(a[0]), "r"(a[1]), "r"(a[2]), "r"(a[3]), "r"(b0), "r"(b1));
}
__device__ __forceinline__ void mma_f(float* c, const uint32_t* a, uint32_t b0, uint32_t b1) {
    asm volatile("mma.sync.aligned.m16n8k16.row.col.f32.f16.f16.f32 "
                 "{%0,%1,%2,%3}, {%4,%5,%6,%7}, {%8,%9}, {%0,%1,%2,%3};"
                 : "+f"(c[0]), "+f"(c[1]), "+f"(c[2]), "+f"(c[3])
                 : "r"(a[0]), "r"(a[1]), "r"(a[2]), "r"(a[3]), "r"(b0), "r"(b1));
}

// ======================= templated per-CTA body ===================
// MT = number of 16-row m-tiles per warp (2 = big CTA, 1 = small CTA).
template <int MT>
__device__ __forceinline__ void flow_body(
    long rowStart, const float* __restrict__ x0, float* __restrict__ out,
    uint32_t sbase, const uint32_t* sb1p, const uint32_t* stw1p,
    const uint32_t* sb2p, const float* sdb3)
{
    const int tid  = threadIdx.x;
    const int wid  = tid >> 5;
    const int lane = tid & 31;
    const int r = lane & 7, g = lane >> 3;
    const uint32_t ld_row = (uint32_t)((r + ((g >> 1) << 3)) * 128);
    const uint32_t g1 = (uint32_t)(g & 1);
    #define KOFF(kt) ((((uint32_t)(((kt) << 1) | g1) ^ (uint32_t)r) << 4))

    const float dt = 1.0f / NSTEPS;
    const uint32_t h05 = 0x38003800u;
    const long rowBase = rowStart + wid * (MT * 16) + (lane >> 2);
    const int  q2 = (lane & 3) * 2;
    const int  l4 = lane & 3;

    float x[MT * 32];
    #pragma unroll
    for (int mt = 0; mt < MT; mt++) {
        const float* pA = x0 + (rowBase + mt * 16) * DIMX;
        const float* pB = x0 + (rowBase + mt * 16 + 8) * DIMX;
        #pragma unroll
        for (int nt = 0; nt < 8; nt++) {
            float2 a = *(const float2*)(pA + nt * 8 + q2);
            float2 b = *(const float2*)(pB + nt * 8 + q2);
            x[(mt * 8 + nt) * 4 + 0] = a.x; x[(mt * 8 + nt) * 4 + 1] = a.y;
            x[(mt * 8 + nt) * 4 + 2] = b.x; x[(mt * 8 + nt) * 4 + 3] = b.y;
        }
    }

    uint32_t hA[MT * 64];   // GEMM2 A fragments (f16x2): [(kt*MT+mt)*4 + j]

    #pragma unroll 1
    for (int s = 0; s < NSTEPS; s++) {
        const float tvalf = ((float)s + 0.5f) * dt;
        const uint32_t tval2 = pack_f16x2(tvalf, tvalf);

        // ---- x -> f16 A fragments for GEMM1 ----
        uint32_t xA[MT * 16];
        #pragma unroll
        for (int kt = 0; kt < 4; kt++) {
            #pragma unroll
            for (int mt = 0; mt < MT; mt++) {
                const float* xs = x + (mt * 8 + 2 * kt) * 4;
                uint32_t* a = xA + (kt * MT + mt) * 4;
                a[0] = pack_f16x2(xs[0], xs[1]);
                a[1] = pack_f16x2(xs[2], xs[3]);
                a[2] = pack_f16x2(xs[4], xs[5]);
                a[3] = pack_f16x2(xs[6], xs[7]);
            }
        }

        // ======== GEMM1: h = silu(x@W1 + b1 + t*tw1), f16 accum ========
        #pragma unroll
        for (int pair = 0; pair < 16; pair++) {
            const uint32_t biasA = hfma2(tval2, stw1p[pair * 8 + l4],     sb1p[pair * 8 + l4]);
            const uint32_t biasB = hfma2(tval2, stw1p[pair * 8 + 4 + l4], sb1p[pair * 8 + 4 + l4]);
            uint32_t C[MT * 4];
            #pragma unroll
            for (int mt = 0; mt < MT; mt++) {
                C[mt * 4 + 0] = biasA; C[mt * 4 + 1] = biasA;
                C[mt * 4 + 2] = biasB; C[mt * 4 + 3] = biasB;
            }
            const uint32_t base = sbase + SM_W1 + (uint32_t)(pair * 2048) + ld_row;
            #pragma unroll
            for (int kt = 0; kt < 4; kt++) {
                uint32_t w0, w1_, w2_, w3_;
                ldsm4(w0, w1_, w2_, w3_, base + KOFF(kt));
                #pragma unroll
                for (int mt = 0; mt < MT; mt++) {
                    mma_h(C + mt * 4 + 0, xA + (kt * MT + mt) * 4, w0,  w1_);
                    mma_h(C + mt * 4 + 2, xA + (kt * MT + mt) * 4, w2_, w3_);
                }
            }
            #pragma unroll
            for (int mt = 0; mt < MT; mt++) {
                uint32_t* h = hA + (pair * MT + mt) * 4;
                h[0] = silu2h(C[mt * 4 + 0], h05);
                h[1] = silu2h(C[mt * 4 + 1], h05);
                h[2] = silu2h(C[mt * 4 + 2], h05);
                h[3] = silu2h(C[mt * 4 + 3], h05);
            }
        }

        // ==== GEMM2 (f16 accum) fused with GEMM3 (f32 accum into x) ====
        #pragma unroll 1
        for (int ch = 0; ch < 8; ch++) {
            uint32_t C2h[MT * 8];   // [(nt*MT+mt)*2 + {0,1}], nt=0..3
            #pragma unroll
            for (int nt = 0; nt < 4; nt++) {
                const uint32_t b2v = sb2p[ch * 16 + nt * 4 + l4];
                #pragma unroll
                for (int mt = 0; mt < MT; mt++) {
                    C2h[(nt * MT + mt) * 2 + 0] = b2v;
                    C2h[(nt * MT + mt) * 2 + 1] = b2v;
                }
            }

            const uint32_t w2base = sbase + SM_W2 + (uint32_t)(ch * 4096) + ld_row;
            uint32_t B0[4], B1[4];
            ldsm4(B0[0], B0[1], B0[2], B0[3], w2base + KOFF(0));
            ldsm4(B1[0], B1[1], B1[2], B1[3], w2base + 2048u + KOFF(0));
            #pragma unroll
            for (int kt = 0; kt < 16; kt++) {
                uint32_t N0[4], N1[4];
                if (kt < 15) {
                    const int kn = kt + 1;
                    const uint32_t ko = (uint32_t)((kn >> 2) * 32768) + KOFF(kn & 3);
                    ldsm4(N0[0], N0[1], N0[2], N0[3], w2base + ko);
                    ldsm4(N1[0], N1[1], N1[2], N1[3], w2base + 2048u + ko);
                }
                #pragma unroll
                for (int mt = 0; mt < MT; mt++) {
                    const uint32_t* a = hA + (kt * MT + mt) * 4;
                    mma_h(C2h + (0 * MT + mt) * 2, a, B0[0], B0[1]);
                    mma_h(C2h + (1 * MT + mt) * 2, a, B0[2], B0[3]);
                    mma_h(C2h + (2 * MT + mt) * 2, a, B1[0], B1[1]);
                    mma_h(C2h + (3 * MT + mt) * 2, a, B1[2], B1[3]);
                }
                if (kt < 15) {
                    #pragma unroll
                    for (int j = 0; j < 4; j++) { B0[j] = N0[j]; B1[j] = N1[j]; }
                }
            }

            // ---- epilogue: in-place SIMD silu -> GEMM3 A fragments ----
            #pragma unroll
            for (int i = 0; i < MT * 8; i++) C2h[i] = silu2h(C2h[i], h05);

            // ---- GEMM3 k-slices: x += silu(C2) @ (dt*W3) ----
            #pragma unroll
            for (int p = 0; p < 2; p++) {
                uint32_t a[MT][4];
                #pragma unroll
                for (int mt = 0; mt < MT; mt++) {
                    a[mt][0] = C2h[((2 * p) * MT + mt) * 2 + 0];
                    a[mt][1] = C2h[((2 * p) * MT + mt) * 2 + 1];
                    a[mt][2] = C2h[((2 * p + 1) * MT + mt) * 2 + 0];
                    a[mt][3] = C2h[((2 * p + 1) * MT + mt) * 2 + 1];
                }
                const int kt3 = ch * 2 + p;
                const uint32_t w3base = sbase + SM_W3 + (uint32_t)((kt3 >> 2) * 8192) + ld_row;
                const uint32_t k3off = KOFF(kt3 & 3);
                #pragma unroll
                for (int ntp = 0; ntp < 4; ntp++) {
                    uint32_t w0, w1_, w2_, w3_;
                    ldsm4(w0, w1_, w2_, w3_, w3base + (uint32_t)(ntp * 2048) + k3off);
                    #pragma unroll
                    for (int mt = 0; mt < MT; mt++) {
                        mma_f(x + (mt * 8 + 2 * ntp) * 4,     a[mt], w0,  w1_);
                        mma_f(x + (mt * 8 + 2 * ntp + 1) * 4, a[mt], w2_, w3_);
                    }
                }
            }
        }

        // ---- x += dt * b3 ----
        #pragma unroll
        for (int nt = 0; nt < 8; nt++) {
            float2 p = *(const float2*)(sdb3 + nt * 8 + q2);
            #pragma unroll
            for (int mt = 0; mt < MT; mt++) {
                float* xs = x + (mt * 8 + nt) * 4;
                xs[0] += p.x; xs[1] += p.y; xs[2] += p.x; xs[3] += p.y;
            }
        }
    }

    // ---- store result ----
    #pragma unroll
    for (int mt = 0; mt < MT; mt++) {
        float* pA = out + (rowBase + mt * 16) * DIMX;
        float* pB = out + (rowBase + mt * 16 + 8) * DIMX;
        #pragma unroll
        for (int nt = 0; nt < 8; nt++) {
            const float* xs = x + (mt * 8 + nt) * 4;
            *(float2*)(pA + nt * 8 + q2) = make_float2(xs[0], xs[1]);
            *(float2*)(pB + nt * 8 + q2) = make_float2(xs[2], xs[3]);
        }
    }
    #undef KOFF
}

// ======================= kernel ==================================
__global__ void __launch_bounds__(NTHREADS, 1) flow_kernel(
    const float* __restrict__ x0, const float* __restrict__ W1,
    const float* __restrict__ b1, const float* __restrict__ W2,
    const float* __restrict__ b2, const float* __restrict__ W3,
    const float* __restrict__ b3, float* __restrict__ out)
{
    extern __shared__ char smem[];
    const uint32_t sbase = smem_to_u32(smem);
    const int tid = threadIdx.x;

    uint32_t* sb1p  = (uint32_t*)(smem + SM_B1P);
    uint32_t* stw1p = (uint32_t*)(smem + SM_TW1P);
    uint32_t* sb2p  = (uint32_t*)(smem + SM_B2P);
    float*    sdb3  = (float*)(smem + SM_DB3);

    const float dt = 1.0f / NSTEPS;

    // ---------------- prologue: packed biases ----------------
    if (tid < 128) {
        sb1p[tid]  = pack_f16x2(b1[2 * tid], b1[2 * tid + 1]);
        stw1p[tid] = pack_f16x2(W1[DIMX * HIDX + 2 * tid], W1[DIMX * HIDX + 2 * tid + 1]);
        sb2p[tid]  = pack_f16x2(b2[2 * tid], b2[2 * tid + 1]);
    }
    if (tid < DIMX) sdb3[tid] = dt * b3[tid];

    // ---------------- prologue: weights -> f16, W^T layout, SW128 ----------------
    for (int idx = tid; idx < DIMX * HIDX; idx += NTHREADS) {          // W1 (64k,256n)
        int k = idx >> 8, n = idx & 255;
        uint32_t off = (uint32_t)(n * 128 + k * 2);
        *(__half*)(smem + SM_W1 + SWZ(off)) = __float2half(W1[idx]);
    }
    for (int idx = tid; idx < HIDX * HIDX; idx += NTHREADS) {          // W2 (256k,256n)
        int k = idx >> 8, n = idx & 255;
        int c = k >> 6, kk = k & 63;
        uint32_t off = (uint32_t)(n * 128 + kk * 2);
        *(__half*)(smem + SM_W2 + c * 32768 + SWZ(off)) = __float2half(W2[idx]);
    }
    for (int idx = tid; idx < HIDX * DIMX; idx += NTHREADS) {          // W3 (256k,64n), x dt
        int k = idx >> 6, n = idx & 63;
        int c = k >> 6, kk = k & 63;
        uint32_t off = (uint32_t)(n * 128 + kk * 2);
        *(__half*)(smem + SM_W3 + c * 8192 + SWZ(off)) = __float2half(dt * W3[idx]);
    }
    __syncthreads();

    if (blockIdx.x < NBIG) {
        flow_body<2>((long)blockIdx.x * 256, x0, out, sbase, sb1p, stw1p, sb2p, sdb3);
    } else {
        flow_body<1>((long)BIGROWS + (long)(blockIdx.x - NBIG) * 128,
                     x0, out, sbase, sb1p, stw1p, sb2p, sdb3);
    }
}

// ======================= launch ==================================
extern "C" void kernel_launch(void* const* d_in, const int* in_sizes, int n_in,
                              void* d_out, int out_size) {
    const float* x0 = (const float*)d_in[0];
    const float* W1 = (const float*)d_in[1];
    const float* b1 = (const float*)d_in[2];
    const float* W2 = (const float*)d_in[3];
    const float* b2 = (const float*)d_in[4];
    const float* W3 = (const float*)d_in[5];
    const float* b3 = (const float*)d_in[6];
    float* out = (float*)d_out;

    const int grid = NBIG + NSMALL;   // 580

    cudaFuncSetAttribute(flow_kernel, cudaFuncAttributeMaxDynamicSharedMemorySize, SMEM_BYTES);
    flow_kernel<<<grid, NTHREADS, SMEM_BYTES>>>(x0, W1, b1, W2, b2, W3, b3, out);
}

// round 11
// speedup vs baseline: 1.2909x; 1.0139x over previous
#include <cuda_runtime.h>
#include <cuda_fp16.h>
#include <cstdint>

// ======================= problem constants =======================
#define DIMX     64
#define HIDX     256
#define NSTEPS   32
#define NTHREADS 256

// two-size grid: 444 big CTAs (256 rows, m32/warp) ~ 3 waves,
// then 136 small CTAs (128 rows, m16/warp) backfill the tail.
#define NBIG     444
#define NSMALL   136
#define BIGROWS  (NBIG * 256)

// ======================= SMEM layout (bytes) =====================
#define SM_B1P  0
#define SM_TW1P 512
#define SM_B2P  1024
#define SM_DB3  3072
#define SM_W1   4096
#define SM_W2   36864
#define SM_W3   167936
#define SMEM_BYTES 200704

#define SWZ(off) ((off) ^ (((off) >> 3) & 0x70))

// ======================= device helpers ==========================
__device__ __forceinline__ uint32_t smem_to_u32(const void* p) {
    uint32_t a;
    asm("{ .reg .u64 t; cvta.to.shared.u64 t, %1; cvt.u32.u64 %0, t; }" : "=r"(a) : "l"(p));
    return a;
}
__device__ __forceinline__ uint32_t pack_f16x2(float lo, float hi) {
    uint32_t r;
    asm("cvt.rn.f16x2.f32 %0, %1, %2;" : "=r"(r) : "f"(hi), "f"(lo));
    return r;
}
__device__ __forceinline__ uint32_t silu2h(uint32_t ah, uint32_t h05) {
    uint32_t t, s, h;
    asm("mul.rn.f16x2 %0, %1, %2;"     : "=r"(t) : "r"(ah), "r"(h05));
    asm("tanh.approx.f16x2 %0, %1;"    : "=r"(t) : "r"(t));
    asm("fma.rn.f16x2 %0, %1, %2, %2;" : "=r"(s) : "r"(t), "r"(h05));
    asm("mul.rn.f16x2 %0, %1, %2;"     : "=r"(h) : "r"(ah), "r"(s));
    return h;
}
__device__ __forceinline__ uint32_t hfma2(uint32_t a, uint32_t b, uint32_t c) {
    uint32_t r;
    asm("fma.rn.f16x2 %0, %1, %2, %3;" : "=r"(r) : "r"(a), "r"(b), "r"(c));
    return r;
}
__device__ __forceinline__ void ldsm4(uint32_t& r0, uint32_t& r1, uint32_t& r2, uint32_t& r3,
                                      uint32_t addr) {
    asm volatile("ldmatrix.sync.aligned.m8n8.x4.shared.b16 {%0,%1,%2,%3}, [%4];"
                 : "=r"(r0), "=r"(r1), "=r"(r2), "=r"(r3) : "r"(addr));
}
__device__ __forceinline__ void mma_h(uint32_t* d, const uint32_t* a, uint32_t b0, uint32_t b1) {
    asm volatile("mma.sync.aligned.m16n8k16.row.col.f16.f16.f16.f16 "
                 "{%0,%1}, {%2,%3,%4,%5}, {%6,%7}, {%0,%1};"
                 : "+r"(d[0]), "+r"(d[1])
                 : "r"(a[0]), "r"(a[1]), "r"(a[2]), "r"(a[3]), "r"(b0), "r"(b1));
}
__device__ __forceinline__ void mma_f(float* c, const uint32_t* a, uint32_t b0, uint32_t b1) {
    asm volatile("mma.sync.aligned.m16n8k16.row.col.f32.f16.f16.f32 "
                 "{%0,%1,%2,%3}, {%4,%5,%6,%7}, {%8,%9}, {%0,%1,%2,%3};"
                 : "+f"(c[0]), "+f"(c[1]), "+f"(c[2]), "+f"(c[3])
                 : "r"(a[0]), "r"(a[1]), "r"(a[2]), "r"(a[3]), "r"(b0), "r"(b1));
}

// ======================= templated per-CTA body ===================
template <int MT>
__device__ __forceinline__ void flow_body(
    long rowStart, const float* __restrict__ x0, float* __restrict__ out,
    uint32_t sbase, const uint32_t* sb1p, const uint32_t* stw1p,
    const uint32_t* sb2p, const float* sdb3)
{
    const int tid  = threadIdx.x;
    const int wid  = tid >> 5;
    const int lane = tid & 31;
    const int r = lane & 7, g = lane >> 3;
    const uint32_t ld_row = (uint32_t)((r + ((g >> 1) << 3)) * 128);
    const uint32_t g1 = (uint32_t)(g & 1);
    #define KOFF(kt) ((((uint32_t)(((kt) << 1) | g1) ^ (uint32_t)r) << 4))

    const float dt = 1.0f / NSTEPS;
    const uint32_t h05 = 0x38003800u;
    const long rowBase = rowStart + wid * (MT * 16) + (lane >> 2);
    const int  q2 = (lane & 3) * 2;
    const int  l4 = lane & 3;

    float x[MT * 32];
    #pragma unroll
    for (int mt = 0; mt < MT; mt++) {
        const float* pA = x0 + (rowBase + mt * 16) * DIMX;
        const float* pB = x0 + (rowBase + mt * 16 + 8) * DIMX;
        #pragma unroll
        for (int nt = 0; nt < 8; nt++) {
            float2 a = *(const float2*)(pA + nt * 8 + q2);
            float2 b = *(const float2*)(pB + nt * 8 + q2);
            x[(mt * 8 + nt) * 4 + 0] = a.x; x[(mt * 8 + nt) * 4 + 1] = a.y;
            x[(mt * 8 + nt) * 4 + 2] = b.x; x[(mt * 8 + nt) * 4 + 3] = b.y;
        }
    }

    uint32_t hA[MT * 64];   // GEMM1 accum -> (after in-place silu) GEMM2 A frags

    #pragma unroll 1
    for (int s = 0; s < NSTEPS; s++) {
        const float tvalf = ((float)s + 0.5f) * dt;
        const uint32_t tval2 = pack_f16x2(tvalf, tvalf);

        // ======== GEMM1 (k-outer, f16 accum in hA) ========
        // 1) bias-init all accumulators
        #pragma unroll
        for (int pair = 0; pair < 16; pair++) {
            const uint32_t biasA = hfma2(tval2, stw1p[pair * 8 + l4],     sb1p[pair * 8 + l4]);
            const uint32_t biasB = hfma2(tval2, stw1p[pair * 8 + 4 + l4], sb1p[pair * 8 + 4 + l4]);
            #pragma unroll
            for (int mt = 0; mt < MT; mt++) {
                uint32_t* h = hA + (pair * MT + mt) * 4;
                h[0] = biasA; h[1] = biasA; h[2] = biasB; h[3] = biasB;
            }
        }
        // 2) accumulate over K (4 k-tiles); 16 independent chains per kt
        #pragma unroll
        for (int kt = 0; kt < 4; kt++) {
            uint32_t xk[MT * 4];
            #pragma unroll
            for (int mt = 0; mt < MT; mt++) {
                const float* xs = x + (mt * 8 + 2 * kt) * 4;
                xk[mt * 4 + 0] = pack_f16x2(xs[0], xs[1]);
                xk[mt * 4 + 1] = pack_f16x2(xs[2], xs[3]);
                xk[mt * 4 + 2] = pack_f16x2(xs[4], xs[5]);
                xk[mt * 4 + 3] = pack_f16x2(xs[6], xs[7]);
            }
            const uint32_t koff = KOFF(kt);
            #pragma unroll
            for (int pair = 0; pair < 16; pair++) {
                uint32_t w0, w1_, w2_, w3_;
                ldsm4(w0, w1_, w2_, w3_,
                      sbase + SM_W1 + (uint32_t)(pair * 2048) + ld_row + koff);
                #pragma unroll
                for (int mt = 0; mt < MT; mt++) {
                    mma_h(hA + (pair * MT + mt) * 4 + 0, xk + mt * 4, w0,  w1_);
                    mma_h(hA + (pair * MT + mt) * 4 + 2, xk + mt * 4, w2_, w3_);
                }
            }
        }
        // 3) in-place SIMD silu -> GEMM2 A fragments
        #pragma unroll
        for (int i = 0; i < MT * 64; i++) hA[i] = silu2h(hA[i], h05);

        // ==== GEMM2 (f16 accum) fused with GEMM3 (f32 accum into x) ====
        #pragma unroll 1
        for (int ch = 0; ch < 8; ch++) {
            uint32_t C2h[MT * 8];   // [(nt*MT+mt)*2 + {0,1}], nt=0..3
            #pragma unroll
            for (int nt = 0; nt < 4; nt++) {
                const uint32_t b2v = sb2p[ch * 16 + nt * 4 + l4];
                #pragma unroll
                for (int mt = 0; mt < MT; mt++) {
                    C2h[(nt * MT + mt) * 2 + 0] = b2v;
                    C2h[(nt * MT + mt) * 2 + 1] = b2v;
                }
            }

            const uint32_t w2base = sbase + SM_W2 + (uint32_t)(ch * 4096) + ld_row;
            uint32_t B0[4], B1[4];
            ldsm4(B0[0], B0[1], B0[2], B0[3], w2base + KOFF(0));
            ldsm4(B1[0], B1[1], B1[2], B1[3], w2base + 2048u + KOFF(0));
            #pragma unroll
            for (int kt = 0; kt < 16; kt++) {
                uint32_t N0[4], N1[4];
                if (kt < 15) {
                    const int kn = kt + 1;
                    const uint32_t ko = (uint32_t)((kn >> 2) * 32768) + KOFF(kn & 3);
                    ldsm4(N0[0], N0[1], N0[2], N0[3], w2base + ko);
                    ldsm4(N1[0], N1[1], N1[2], N1[3], w2base + 2048u + ko);
                }
                #pragma unroll
                for (int mt = 0; mt < MT; mt++) {
                    const uint32_t* a = hA + (kt * MT + mt) * 4;
                    mma_h(C2h + (0 * MT + mt) * 2, a, B0[0], B0[1]);
                    mma_h(C2h + (1 * MT + mt) * 2, a, B0[2], B0[3]);
                    mma_h(C2h + (2 * MT + mt) * 2, a, B1[0], B1[1]);
                    mma_h(C2h + (3 * MT + mt) * 2, a, B1[2], B1[3]);
                }
                if (kt < 15) {
                    #pragma unroll
                    for (int j = 0; j < 4; j++) { B0[j] = N0[j]; B1[j] = N1[j]; }
                }
            }

            // ---- GEMM3 p=0 weight fragments hoisted ABOVE the silu epilogue ----
            const uint32_t w3baseA = sbase + SM_W3 + (uint32_t)(((ch * 2) >> 2) * 8192) + ld_row;
            const uint32_t k3offA  = KOFF((ch * 2) & 3);
            uint32_t W3f[16];
            #pragma unroll
            for (int ntp = 0; ntp < 4; ntp++)
                ldsm4(W3f[ntp * 4 + 0], W3f[ntp * 4 + 1], W3f[ntp * 4 + 2], W3f[ntp * 4 + 3],
                      w3baseA + (uint32_t)(ntp * 2048) + k3offA);

            // ---- epilogue: in-place SIMD silu (overlaps W3f ldsm latency) ----
            #pragma unroll
            for (int i = 0; i < MT * 8; i++) C2h[i] = silu2h(C2h[i], h05);

            // ---- GEMM3 p=0: x += silu(C2)[k-lo] @ (dt*W3) ----
            {
                uint32_t a[MT][4];
                #pragma unroll
                for (int mt = 0; mt < MT; mt++) {
                    a[mt][0] = C2h[(0 * MT + mt) * 2 + 0];
                    a[mt][1] = C2h[(0 * MT + mt) * 2 + 1];
                    a[mt][2] = C2h[(1 * MT + mt) * 2 + 0];
                    a[mt][3] = C2h[(1 * MT + mt) * 2 + 1];
                }
                #pragma unroll
                for (int ntp = 0; ntp < 4; ntp++) {
                    #pragma unroll
                    for (int mt = 0; mt < MT; mt++) {
                        mma_f(x + (mt * 8 + 2 * ntp) * 4,     a[mt], W3f[ntp * 4 + 0], W3f[ntp * 4 + 1]);
                        mma_f(x + (mt * 8 + 2 * ntp + 1) * 4, a[mt], W3f[ntp * 4 + 2], W3f[ntp * 4 + 3]);
                    }
                }
            }
            // ---- GEMM3 p=1 ----
            {
                uint32_t a[MT][4];
                #pragma unroll
                for (int mt = 0; mt < MT; mt++) {
                    a[mt][0] = C2h[(2 * MT + mt) * 2 + 0];
                    a[mt][1] = C2h[(2 * MT + mt) * 2 + 1];
                    a[mt][2] = C2h[(3 * MT + mt) * 2 + 0];
                    a[mt][3] = C2h[(3 * MT + mt) * 2 + 1];
                }
                const int kt3 = ch * 2 + 1;
                const uint32_t w3base = sbase + SM_W3 + (uint32_t)((kt3 >> 2) * 8192) + ld_row;
                const uint32_t k3off = KOFF(kt3 & 3);
                #pragma unroll
                for (int ntp = 0; ntp < 4; ntp++) {
                    uint32_t w0, w1_, w2_, w3_;
                    ldsm4(w0, w1_, w2_, w3_, w3base + (uint32_t)(ntp * 2048) + k3off);
                    #pragma unroll
                    for (int mt = 0; mt < MT; mt++) {
                        mma_f(x + (mt * 8 + 2 * ntp) * 4,     a[mt], w0,  w1_);
                        mma_f(x + (mt * 8 + 2 * ntp + 1) * 4, a[mt], w2_, w3_);
                    }
                }
            }
        }

        // ---- x += dt * b3 ----
        #pragma unroll
        for (int nt = 0; nt < 8; nt++) {
            float2 p = *(const float2*)(sdb3 + nt * 8 + q2);
            #pragma unroll
            for (int mt = 0; mt < MT; mt++) {
                float* xs = x + (mt * 8 + nt) * 4;
                xs[0] += p.x; xs[1] += p.y; xs[2] += p.x; xs[3] += p.y;
            }
        }
    }

    // ---- store result ----
    #pragma unroll
    for (int mt = 0; mt < MT; mt++) {
        float* pA = out + (rowBase + mt * 16) * DIMX;
        float* pB = out + (rowBase + mt * 16 + 8) * DIMX;
        #pragma unroll
        for (int nt = 0; nt < 8; nt++) {
            const float* xs = x + (mt * 8 + nt) * 4;
            *(float2*)(pA + nt * 8 + q2) = make_float2(xs[0], xs[1]);
            *(float2*)(pB + nt * 8 + q2) = make_float2(xs[2], xs[3]);
        }
    }
    #undef KOFF
}

// ======================= kernel ==================================
__global__ void __launch_bounds__(NTHREADS, 1) flow_kernel(
    const float* __restrict__ x0, const float* __restrict__ W1,
    const float* __restrict__ b1, const float* __restrict__ W2,
    const float* __restrict__ b2, const float* __restrict__ W3,
    const float* __restrict__ b3, float* __restrict__ out)
{
    extern __shared__ char smem[];
    const uint32_t sbase = smem_to_u32(smem);
    const int tid = threadIdx.x;

    uint32_t* sb1p  = (uint32_t*)(smem + SM_B1P);
    uint32_t* stw1p = (uint32_t*)(smem + SM_TW1P);
    uint32_t* sb2p  = (uint32_t*)(smem + SM_B2P);
    float*    sdb3  = (float*)(smem + SM_DB3);

    const float dt = 1.0f / NSTEPS;

    if (tid < 128) {
        sb1p[tid]  = pack_f16x2(b1[2 * tid], b1[2 * tid + 1]);
        stw1p[tid] = pack_f16x2(W1[DIMX * HIDX + 2 * tid], W1[DIMX * HIDX + 2 * tid + 1]);
        sb2p[tid]  = pack_f16x2(b2[2 * tid], b2[2 * tid + 1]);
    }
    if (tid < DIMX) sdb3[tid] = dt * b3[tid];

    for (int idx = tid; idx < DIMX * HIDX; idx += NTHREADS) {          // W1 (64k,256n)
        int k = idx >> 8, n = idx & 255;
        uint32_t off = (uint32_t)(n * 128 + k * 2);
        *(__half*)(smem + SM_W1 + SWZ(off)) = __float2half(W1[idx]);
    }
    for (int idx = tid; idx < HIDX * HIDX; idx += NTHREADS) {          // W2 (256k,256n)
        int k = idx >> 8, n = idx & 255;
        int c = k >> 6, kk = k & 63;
        uint32_t off = (uint32_t)(n * 128 + kk * 2);
        *(__half*)(smem + SM_W2 + c * 32768 + SWZ(off)) = __float2half(W2[idx]);
    }
    for (int idx = tid; idx < HIDX * DIMX; idx += NTHREADS) {          // W3 (256k,64n), x dt
        int k = idx >> 6, n = idx & 63;
        int c = k >> 6, kk = k & 63;
        uint32_t off = (uint32_t)(n * 128 + kk * 2);
        *(__half*)(smem + SM_W3 + c * 8192 + SWZ(off)) = __float2half(dt * W3[idx]);
    }
    __syncthreads();

    if (blockIdx.x < NBIG) {
        flow_body<2>((long)blockIdx.x * 256, x0, out, sbase, sb1p, stw1p, sb2p, sdb3);
    } else {
        flow_body<1>((long)BIGROWS + (long)(blockIdx.x - NBIG) * 128,
                     x0, out, sbase, sb1p, stw1p, sb2p, sdb3);
    }
}

// ======================= launch ==================================
extern "C" void kernel_launch(void* const* d_in, const int* in_sizes, int n_in,
                              void* d_out, int out_size) {
    const float* x0 = (const float*)d_in[0];
    const float* W1 = (const float*)d_in[1];
    const float* b1 = (const float*)d_in[2];
    const float* W2 = (const float*)d_in[3];
    const float* b2 = (const float*)d_in[4];
    const float* W3 = (const float*)d_in[5];
    const float* b3 = (const float*)d_in[6];
    float* out = (float*)d_out;

    cudaFuncSetAttribute(flow_kernel, cudaFuncAttributeMaxDynamicSharedMemorySize, SMEM_BYTES);
    flow_kernel<<<NBIG + NSMALL, NTHREADS, SMEM_BYTES>>>(x0, W1, b1, W2, b2, W3, b3, out);
}

// round 12
// speedup vs baseline: 1.3130x; 1.0171x over previous
#include <cuda_runtime.h>
#include <cuda_fp16.h>
#include <cstdint>

// ======================= problem constants =======================
#define DIMX     64
#define HIDX     256
#define NSTEPS   32
#define NTHREADS 256

// two-size grid: 444 big CTAs (256 rows, m32/warp) ~ 3 waves,
// then 136 small CTAs (128 rows, m16/warp) backfill the tail.
#define NBIG     444
#define NSMALL   136
#define BIGROWS  (NBIG * 256)

// ======================= SMEM layout (bytes) =====================
#define SM_B1P  0
#define SM_TW1P 512
#define SM_B2P  1024
#define SM_DB3  3072
#define SM_W1   4096
#define SM_W2   36864
#define SM_W3   167936
#define SMEM_BYTES 200704

#define SWZ(off) ((off) ^ (((off) >> 3) & 0x70))

// ======================= device helpers ==========================
__device__ __forceinline__ uint32_t smem_to_u32(const void* p) {
    uint32_t a;
    asm("{ .reg .u64 t; cvta.to.shared.u64 t, %1; cvt.u32.u64 %0, t; }" : "=r"(a) : "l"(p));
    return a;
}
__device__ __forceinline__ uint32_t pack_f16x2(float lo, float hi) {
    uint32_t r;
    asm("cvt.rn.f16x2.f32 %0, %1, %2;" : "=r"(r) : "f"(hi), "f"(lo));
    return r;
}
__device__ __forceinline__ uint32_t silu2h(uint32_t ah, uint32_t h05) {
    uint32_t t, s, h;
    asm("mul.rn.f16x2 %0, %1, %2;"     : "=r"(t) : "r"(ah), "r"(h05));
    asm("tanh.approx.f16x2 %0, %1;"    : "=r"(t) : "r"(t));
    asm("fma.rn.f16x2 %0, %1, %2, %2;" : "=r"(s) : "r"(t), "r"(h05));
    asm("mul.rn.f16x2 %0, %1, %2;"     : "=r"(h) : "r"(ah), "r"(s));
    return h;
}
__device__ __forceinline__ uint32_t hfma2(uint32_t a, uint32_t b, uint32_t c) {
    uint32_t r;
    asm("fma.rn.f16x2 %0, %1, %2, %3;" : "=r"(r) : "r"(a), "r"(b), "r"(c));
    return r;
}
__device__ __forceinline__ void ldsm4(uint32_t& r0, uint32_t& r1, uint32_t& r2, uint32_t& r3,
                                      uint32_t addr) {
    asm volatile("ldmatrix.sync.aligned.m8n8.x4.shared.b16 {%0,%1,%2,%3}, [%4];"
                 : "=r"(r0), "=r"(r1), "=r"(r2), "=r"(r3) : "r"(addr));
}
__device__ __forceinline__ void mma_h(uint32_t* d, const uint32_t* a, uint32_t b0, uint32_t b1) {
    asm volatile("mma.sync.aligned.m16n8k16.row.col.f16.f16.f16.f16 "
                 "{%0,%1}, {%2,%3,%4,%5}, {%6,%7}, {%0,%1};"
                 : "+r"(d[0]), "+r"(d[1])
                 : "r"(a[0]), "r"(a[1]), "r"(a[2]), "r"(a[3]), "r"(b0), "r"(b1));
}
__device__ __forceinline__ void mma_f(float* c, const uint32_t* a, uint32_t b0, uint32_t b1) {
    asm volatile("mma.sync.aligned.m16n8k16.row.col.f32.f16.f16.f32 "
                 "{%0,%1,%2,%3}, {%4,%5,%6,%7}, {%8,%9}, {%0,%1,%2,%3};"
                 : "+f"(c[0]), "+f"(c[1]), "+f"(c[2]), "+f"(c[3])
                 : "r"(a[0]), "r"(a[1]), "r"(a[2]), "r"(a[3]), "r"(b0), "r"(b1));
}

// ======================= templated per-CTA body ===================
template <int MT>
__device__ __forceinline__ void flow_body(
    long rowStart, const float* __restrict__ x0, float* __restrict__ out,
    uint32_t sbase, const uint32_t* sb1p, const uint32_t* stw1p,
    const uint32_t* sb2p, const float* sdb3)
{
    const int tid  = threadIdx.x;
    const int wid  = tid >> 5;
    const int lane = tid & 31;
    const int r = lane & 7, g = lane >> 3;
    const uint32_t ld_row = (uint32_t)((r + ((g >> 1) << 3)) * 128);
    const uint32_t g1 = (uint32_t)(g & 1);
    #define KOFF(kt) ((((uint32_t)(((kt) << 1) | g1) ^ (uint32_t)r) << 4))

    const float dt = 1.0f / NSTEPS;
    const uint32_t h05 = 0x38003800u;
    const long rowBase = rowStart + wid * (MT * 16) + (lane >> 2);
    const int  q2 = (lane & 3) * 2;
    const int  l4 = lane & 3;

    float x[MT * 32];
    #pragma unroll
    for (int mt = 0; mt < MT; mt++) {
        const float* pA = x0 + (rowBase + mt * 16) * DIMX;
        const float* pB = x0 + (rowBase + mt * 16 + 8) * DIMX;
        #pragma unroll
        for (int nt = 0; nt < 8; nt++) {
            float2 a = *(const float2*)(pA + nt * 8 + q2);
            float2 b = *(const float2*)(pB + nt * 8 + q2);
            x[(mt * 8 + nt) * 4 + 0] = a.x; x[(mt * 8 + nt) * 4 + 1] = a.y;
            x[(mt * 8 + nt) * 4 + 2] = b.x; x[(mt * 8 + nt) * 4 + 3] = b.y;
        }
    }

    uint32_t hA[MT * 64];   // GEMM1 accum -> (after in-place silu) GEMM2 A frags

    // ---- GEMM2 chunk stages (all addresses static under full unroll) ----
    #define G2_INIT(ch, C2) do { \
        _Pragma("unroll") for (int nt = 0; nt < 4; nt++) { \
            const uint32_t b2v = sb2p[(ch) * 16 + nt * 4 + l4]; \
            _Pragma("unroll") for (int mt = 0; mt < MT; mt++) { \
                (C2)[(nt * MT + mt) * 2 + 0] = b2v; \
                (C2)[(nt * MT + mt) * 2 + 1] = b2v; } } } while (0)

    #define G2_MMA(ch, C2) do { \
        const uint32_t w2base = sbase + SM_W2 + (uint32_t)((ch) * 4096) + ld_row; \
        uint32_t B0[4], B1[4]; \
        ldsm4(B0[0], B0[1], B0[2], B0[3], w2base + KOFF(0)); \
        ldsm4(B1[0], B1[1], B1[2], B1[3], w2base + 2048u + KOFF(0)); \
        _Pragma("unroll") for (int kt = 0; kt < 16; kt++) { \
            uint32_t N0[4], N1[4]; \
            if (kt < 15) { \
                const int kn = kt + 1; \
                const uint32_t ko = (uint32_t)((kn >> 2) * 32768) + KOFF(kn & 3); \
                ldsm4(N0[0], N0[1], N0[2], N0[3], w2base + ko); \
                ldsm4(N1[0], N1[1], N1[2], N1[3], w2base + 2048u + ko); } \
            _Pragma("unroll") for (int mt = 0; mt < MT; mt++) { \
                const uint32_t* a = hA + (kt * MT + mt) * 4; \
                mma_h((C2) + (0 * MT + mt) * 2, a, B0[0], B0[1]); \
                mma_h((C2) + (1 * MT + mt) * 2, a, B0[2], B0[3]); \
                mma_h((C2) + (2 * MT + mt) * 2, a, B1[0], B1[1]); \
                mma_h((C2) + (3 * MT + mt) * 2, a, B1[2], B1[3]); } \
            if (kt < 15) { \
                _Pragma("unroll") for (int j = 0; j < 4; j++) { B0[j] = N0[j]; B1[j] = N1[j]; } } \
        } } while (0)

    #define EPI_G3(ch, C2) do { \
        _Pragma("unroll") for (int i = 0; i < MT * 8; i++) (C2)[i] = silu2h((C2)[i], h05); \
        _Pragma("unroll") for (int p = 0; p < 2; p++) { \
            uint32_t af[MT][4]; \
            _Pragma("unroll") for (int mt = 0; mt < MT; mt++) { \
                af[mt][0] = (C2)[((2 * p) * MT + mt) * 2 + 0]; \
                af[mt][1] = (C2)[((2 * p) * MT + mt) * 2 + 1]; \
                af[mt][2] = (C2)[((2 * p + 1) * MT + mt) * 2 + 0]; \
                af[mt][3] = (C2)[((2 * p + 1) * MT + mt) * 2 + 1]; } \
            const int kt3 = (ch) * 2 + p; \
            const uint32_t w3base = sbase + SM_W3 + (uint32_t)((kt3 >> 2) * 8192) + ld_row; \
            const uint32_t k3off = KOFF(kt3 & 3); \
            _Pragma("unroll") for (int ntp = 0; ntp < 4; ntp++) { \
                uint32_t w0, w1_, w2_, w3_; \
                ldsm4(w0, w1_, w2_, w3_, w3base + (uint32_t)(ntp * 2048) + k3off); \
                _Pragma("unroll") for (int mt = 0; mt < MT; mt++) { \
                    mma_f(x + (mt * 8 + 2 * ntp) * 4,     af[mt], w0,  w1_); \
                    mma_f(x + (mt * 8 + 2 * ntp + 1) * 4, af[mt], w2_, w3_); } } } } while (0)

    #pragma unroll 1
    for (int s = 0; s < NSTEPS; s++) {
        const float tvalf = ((float)s + 0.5f) * dt;
        const uint32_t tval2 = pack_f16x2(tvalf, tvalf);

        // ======== GEMM1 (k-outer, f16 accum in hA) ========
        #pragma unroll
        for (int pair = 0; pair < 16; pair++) {
            const uint32_t biasA = hfma2(tval2, stw1p[pair * 8 + l4],     sb1p[pair * 8 + l4]);
            const uint32_t biasB = hfma2(tval2, stw1p[pair * 8 + 4 + l4], sb1p[pair * 8 + 4 + l4]);
            #pragma unroll
            for (int mt = 0; mt < MT; mt++) {
                uint32_t* h = hA + (pair * MT + mt) * 4;
                h[0] = biasA; h[1] = biasA; h[2] = biasB; h[3] = biasB;
            }
        }
        #pragma unroll
        for (int kt = 0; kt < 4; kt++) {
            uint32_t xk[MT * 4];
            #pragma unroll
            for (int mt = 0; mt < MT; mt++) {
                const float* xs = x + (mt * 8 + 2 * kt) * 4;
                xk[mt * 4 + 0] = pack_f16x2(xs[0], xs[1]);
                xk[mt * 4 + 1] = pack_f16x2(xs[2], xs[3]);
                xk[mt * 4 + 2] = pack_f16x2(xs[4], xs[5]);
                xk[mt * 4 + 3] = pack_f16x2(xs[6], xs[7]);
            }
            const uint32_t koff = KOFF(kt);
            #pragma unroll
            for (int pair = 0; pair < 16; pair++) {
                uint32_t w0, w1_, w2_, w3_;
                ldsm4(w0, w1_, w2_, w3_,
                      sbase + SM_W1 + (uint32_t)(pair * 2048) + ld_row + koff);
                #pragma unroll
                for (int mt = 0; mt < MT; mt++) {
                    mma_h(hA + (pair * MT + mt) * 4 + 0, xk + mt * 4, w0,  w1_);
                    mma_h(hA + (pair * MT + mt) * 4 + 2, xk + mt * 4, w2_, w3_);
                }
            }
        }
        // in-place SIMD silu -> GEMM2 A fragments
        #pragma unroll
        for (int i = 0; i < MT * 64; i++) hA[i] = silu2h(hA[i], h05);

        // ==== GEMM2+GEMM3, chunk-level software pipeline (ping-pong C2a/C2b) ====
        // While chunk ch's silu+GEMM3 run (MUFU/FMA), chunk ch+1's 128-mma
        // stream is already issued -> tensor pipe never drains at boundaries.
        {
            uint32_t C2a[MT * 8], C2b[MT * 8];
            G2_INIT(0, C2a); G2_MMA(0, C2a);
            #pragma unroll
            for (int ch = 0; ch < 8; ch += 2) {
                G2_INIT(ch + 1, C2b); G2_MMA(ch + 1, C2b);
                EPI_G3(ch, C2a);
                if (ch < 6) { G2_INIT(ch + 2, C2a); G2_MMA(ch + 2, C2a); }
                EPI_G3(ch + 1, C2b);
            }
        }

        // ---- x += dt * b3 ----
        #pragma unroll
        for (int nt = 0; nt < 8; nt++) {
            float2 p = *(const float2*)(sdb3 + nt * 8 + q2);
            #pragma unroll
            for (int mt = 0; mt < MT; mt++) {
                float* xs = x + (mt * 8 + nt) * 4;
                xs[0] += p.x; xs[1] += p.y; xs[2] += p.x; xs[3] += p.y;
            }
        }
    }

    // ---- store result ----
    #pragma unroll
    for (int mt = 0; mt < MT; mt++) {
        float* pA = out + (rowBase + mt * 16) * DIMX;
        float* pB = out + (rowBase + mt * 16 + 8) * DIMX;
        #pragma unroll
        for (int nt = 0; nt < 8; nt++) {
            const float* xs = x + (mt * 8 + nt) * 4;
            *(float2*)(pA + nt * 8 + q2) = make_float2(xs[0], xs[1]);
            *(float2*)(pB + nt * 8 + q2) = make_float2(xs[2], xs[3]);
        }
    }
    #undef KOFF
    #undef G2_INIT
    #undef G2_MMA
    #undef EPI_G3
}

// ======================= kernel ==================================
__global__ void __launch_bounds__(NTHREADS, 1) flow_kernel(
    const float* __restrict__ x0, const float* __restrict__ W1,
    const float* __restrict__ b1, const float* __restrict__ W2,
    const float* __restrict__ b2, const float* __restrict__ W3,
    const float* __restrict__ b3, float* __restrict__ out)
{
    extern __shared__ char smem[];
    const uint32_t sbase = smem_to_u32(smem);
    const int tid = threadIdx.x;

    uint32_t* sb1p  = (uint32_t*)(smem + SM_B1P);
    uint32_t* stw1p = (uint32_t*)(smem + SM_TW1P);
    uint32_t* sb2p  = (uint32_t*)(smem + SM_B2P);
    float*    sdb3  = (float*)(smem + SM_DB3);

    const float dt = 1.0f / NSTEPS;

    if (tid < 128) {
        sb1p[tid]  = pack_f16x2(b1[2 * tid], b1[2 * tid + 1]);
        stw1p[tid] = pack_f16x2(W1[DIMX * HIDX + 2 * tid], W1[DIMX * HIDX + 2 * tid + 1]);
        sb2p[tid]  = pack_f16x2(b2[2 * tid], b2[2 * tid + 1]);
    }
    if (tid < DIMX) sdb3[tid] = dt * b3[tid];

    for (int idx = tid; idx < DIMX * HIDX; idx += NTHREADS) {          // W1 (64k,256n)
        int k = idx >> 8, n = idx & 255;
        uint32_t off = (uint32_t)(n * 128 + k * 2);
        *(__half*)(smem + SM_W1 + SWZ(off)) = __float2half(W1[idx]);
    }
    for (int idx = tid; idx < HIDX * HIDX; idx += NTHREADS) {          // W2 (256k,256n)
        int k = idx >> 8, n = idx & 255;
        int c = k >> 6, kk = k & 63;
        uint32_t off = (uint32_t)(n * 128 + kk * 2);
        *(__half*)(smem + SM_W2 + c * 32768 + SWZ(off)) = __float2half(W2[idx]);
    }
    for (int idx = tid; idx < HIDX * DIMX; idx += NTHREADS) {          // W3 (256k,64n), x dt
        int k = idx >> 6, n = idx & 63;
        int c = k >> 6, kk = k & 63;
        uint32_t off = (uint32_t)(n * 128 + kk * 2);
        *(__half*)(smem + SM_W3 + c * 8192 + SWZ(off)) = __float2half(dt * W3[idx]);
    }
    __syncthreads();

    if (blockIdx.x < NBIG) {
        flow_body<2>((long)blockIdx.x * 256, x0, out, sbase, sb1p, stw1p, sb2p, sdb3);
    } else {
        flow_body<1>((long)BIGROWS + (long)(blockIdx.x - NBIG) * 128,
                     x0, out, sbase, sb1p, stw1p, sb2p, sdb3);
    }
}

// ======================= launch ==================================
extern "C" void kernel_launch(void* const* d_in, const int* in_sizes, int n_in,
                              void* d_out, int out_size) {
    const float* x0 = (const float*)d_in[0];
    const float* W1 = (const float*)d_in[1];
    const float* b1 = (const float*)d_in[2];
    const float* W2 = (const float*)d_in[3];
    const float* b2 = (const float*)d_in[4];
    const float* W3 = (const float*)d_in[5];
    const float* b3 = (const float*)d_in[6];
    float* out = (float*)d_out;

    cudaFuncSetAttribute(flow_kernel, cudaFuncAttributeMaxDynamicSharedMemorySize, SMEM_BYTES);
    flow_kernel<<<NBIG + NSMALL, NTHREADS, SMEM_BYTES>>>(x0, W1, b1, W2, b2, W3, b3, out);
}

// round 13
// speedup vs baseline: 1.3149x; 1.0014x over previous
#include <cuda_runtime.h>
#include <cuda_fp16.h>
#include <cstdint>

// ======================= problem constants =======================
#define DIMX     64
#define HIDX     256
#define NSTEPS   32
#define NTHREADS 256

// two-size grid: 444 big CTAs (256 rows, m32/warp) ~ 3 waves,
// then 136 small CTAs (128 rows, m16/warp) backfill the tail.
#define NBIG     444
#define NSMALL   136
#define BIGROWS  (NBIG * 256)

// ======================= SMEM layout (bytes) =====================
#define SM_B1P  0
#define SM_TW1P 512
#define SM_B2P  1024
#define SM_DB3  3072
#define SM_W1   4096
#define SM_W2   36864
#define SM_W3   167936
#define SMEM_BYTES 200704

#define SWZ(off) ((off) ^ (((off) >> 3) & 0x70))

// ======================= device helpers ==========================
__device__ __forceinline__ uint32_t smem_to_u32(const void* p) {
    uint32_t a;
    asm("{ .reg .u64 t; cvta.to.shared.u64 t, %1; cvt.u32.u64 %0, t; }" : "=r"(a) : "l"(p));
    return a;
}
__device__ __forceinline__ uint32_t pack_f16x2(float lo, float hi) {
    uint32_t r;
    asm("cvt.rn.f16x2.f32 %0, %1, %2;" : "=r"(r) : "f"(hi), "f"(lo));
    return r;
}
__device__ __forceinline__ uint32_t silu2h(uint32_t ah, uint32_t h05) {
    uint32_t t, s, h;
    asm("mul.rn.f16x2 %0, %1, %2;"     : "=r"(t) : "r"(ah), "r"(h05));
    asm("tanh.approx.f16x2 %0, %1;"    : "=r"(t) : "r"(t));
    asm("fma.rn.f16x2 %0, %1, %2, %2;" : "=r"(s) : "r"(t), "r"(h05));
    asm("mul.rn.f16x2 %0, %1, %2;"     : "=r"(h) : "r"(ah), "r"(s));
    return h;
}
__device__ __forceinline__ uint32_t hfma2(uint32_t a, uint32_t b, uint32_t c) {
    uint32_t r;
    asm("fma.rn.f16x2 %0, %1, %2, %3;" : "=r"(r) : "r"(a), "r"(b), "r"(c));
    return r;
}
__device__ __forceinline__ void ldsm4(uint32_t& r0, uint32_t& r1, uint32_t& r2, uint32_t& r3,
                                      uint32_t addr) {
    asm volatile("ldmatrix.sync.aligned.m8n8.x4.shared.b16 {%0,%1,%2,%3}, [%4];"
                 : "=r"(r0), "=r"(r1), "=r"(r2), "=r"(r3) : "r"(addr));
}
__device__ __forceinline__ void mma_h(uint32_t* d, const uint32_t* a, uint32_t b0, uint32_t b1) {
    asm volatile("mma.sync.aligned.m16n8k16.row.col.f16.f16.f16.f16 "
                 "{%0,%1}, {%2,%3,%4,%5}, {%6,%7}, {%0,%1};"
                 : "+r"(d[0]), "+r"(d[1])
                 : "r"(a[0]), "r"(a[1]), "r"(a[2]), "r"(a[3]), "r"(b0), "r"(b1));
}
__device__ __forceinline__ void mma_f(float* c, const uint32_t* a, uint32_t b0, uint32_t b1) {
    asm volatile("mma.sync.aligned.m16n8k16.row.col.f32.f16.f16.f32 "
                 "{%0,%1,%2,%3}, {%4,%5,%6,%7}, {%8,%9}, {%0,%1,%2,%3};"
                 : "+f"(c[0]), "+f"(c[1]), "+f"(c[2]), "+f"(c[3])
                 : "r"(a[0]), "r"(a[1]), "r"(a[2]), "r"(a[3]), "r"(b0), "r"(b1));
}

// ======================= templated per-CTA body ===================
template <int MT>
__device__ __forceinline__ void flow_body(
    long rowStart, const float* __restrict__ x0, float* __restrict__ out,
    uint32_t sbase, const uint32_t* sb1p, const uint32_t* stw1p,
    const uint32_t* sb2p, const float* sdb3)
{
    const int tid  = threadIdx.x;
    const int wid  = tid >> 5;
    const int lane = tid & 31;
    const int r = lane & 7, g = lane >> 3;
    const uint32_t ld_row = (uint32_t)((r + ((g >> 1) << 3)) * 128);
    const uint32_t g1 = (uint32_t)(g & 1);
    #define KOFF(kt) ((((uint32_t)(((kt) << 1) | g1) ^ (uint32_t)r) << 4))

    const float dt = 1.0f / NSTEPS;
    const uint32_t h05 = 0x38003800u;
    const long rowBase = rowStart + wid * (MT * 16) + (lane >> 2);
    const int  q2 = (lane & 3) * 2;
    const int  l4 = lane & 3;

    float x[MT * 32];
    #pragma unroll
    for (int mt = 0; mt < MT; mt++) {
        const float* pA = x0 + (rowBase + mt * 16) * DIMX;
        const float* pB = x0 + (rowBase + mt * 16 + 8) * DIMX;
        #pragma unroll
        for (int nt = 0; nt < 8; nt++) {
            float2 a = *(const float2*)(pA + nt * 8 + q2);
            float2 b = *(const float2*)(pB + nt * 8 + q2);
            x[(mt * 8 + nt) * 4 + 0] = a.x; x[(mt * 8 + nt) * 4 + 1] = a.y;
            x[(mt * 8 + nt) * 4 + 2] = b.x; x[(mt * 8 + nt) * 4 + 3] = b.y;
        }
    }

    uint32_t hA[MT * 64];   // GEMM1 accum -> (after fused silu) GEMM2 A frags

    // silu one k-slice (8 words for MT=2) of hA in place
    #define SILU_SLICE(kt) do { \
        _Pragma("unroll") for (int mt = 0; mt < MT; mt++) { \
            uint32_t* h = hA + ((kt) * MT + mt) * 4; \
            h[0] = silu2h(h[0], h05); h[1] = silu2h(h[1], h05); \
            h[2] = silu2h(h[2], h05); h[3] = silu2h(h[3], h05); } } while (0)

    #define G2_INIT(ch, C2) do { \
        _Pragma("unroll") for (int nt = 0; nt < 4; nt++) { \
            const uint32_t b2v = sb2p[(ch) * 16 + nt * 4 + l4]; \
            _Pragma("unroll") for (int mt = 0; mt < MT; mt++) { \
                (C2)[(nt * MT + mt) * 2 + 0] = b2v; \
                (C2)[(nt * MT + mt) * 2 + 1] = b2v; } } } while (0)

    // FUSE_SILU: chunk 0 applies silu to hA slice kt+1 while slice kt's mmas issue.
    #define G2_MMA(ch, C2, FUSE_SILU) do { \
        const uint32_t w2base = sbase + SM_W2 + (uint32_t)((ch) * 4096) + ld_row; \
        uint32_t B0[4], B1[4]; \
        ldsm4(B0[0], B0[1], B0[2], B0[3], w2base + KOFF(0)); \
        ldsm4(B1[0], B1[1], B1[2], B1[3], w2base + 2048u + KOFF(0)); \
        _Pragma("unroll") for (int kt = 0; kt < 16; kt++) { \
            uint32_t N0[4], N1[4]; \
            if (kt < 15) { \
                const int kn = kt + 1; \
                const uint32_t ko = (uint32_t)((kn >> 2) * 32768) + KOFF(kn & 3); \
                ldsm4(N0[0], N0[1], N0[2], N0[3], w2base + ko); \
                ldsm4(N1[0], N1[1], N1[2], N1[3], w2base + 2048u + ko); } \
            if ((FUSE_SILU) && kt < 15) SILU_SLICE(kt + 1); \
            _Pragma("unroll") for (int mt = 0; mt < MT; mt++) { \
                const uint32_t* a = hA + (kt * MT + mt) * 4; \
                mma_h((C2) + (0 * MT + mt) * 2, a, B0[0], B0[1]); \
                mma_h((C2) + (1 * MT + mt) * 2, a, B0[2], B0[3]); \
                mma_h((C2) + (2 * MT + mt) * 2, a, B1[0], B1[1]); \
                mma_h((C2) + (3 * MT + mt) * 2, a, B1[2], B1[3]); } \
            if (kt < 15) { \
                _Pragma("unroll") for (int j = 0; j < 4; j++) { B0[j] = N0[j]; B1[j] = N1[j]; } } \
        } } while (0)

    #define EPI_G3(ch, C2) do { \
        _Pragma("unroll") for (int i = 0; i < MT * 8; i++) (C2)[i] = silu2h((C2)[i], h05); \
        _Pragma("unroll") for (int p = 0; p < 2; p++) { \
            uint32_t af[MT][4]; \
            _Pragma("unroll") for (int mt = 0; mt < MT; mt++) { \
                af[mt][0] = (C2)[((2 * p) * MT + mt) * 2 + 0]; \
                af[mt][1] = (C2)[((2 * p) * MT + mt) * 2 + 1]; \
                af[mt][2] = (C2)[((2 * p + 1) * MT + mt) * 2 + 0]; \
                af[mt][3] = (C2)[((2 * p + 1) * MT + mt) * 2 + 1]; } \
            const int kt3 = (ch) * 2 + p; \
            const uint32_t w3base = sbase + SM_W3 + (uint32_t)((kt3 >> 2) * 8192) + ld_row; \
            const uint32_t k3off = KOFF(kt3 & 3); \
            _Pragma("unroll") for (int ntp = 0; ntp < 4; ntp++) { \
                uint32_t w0, w1_, w2_, w3_; \
                ldsm4(w0, w1_, w2_, w3_, w3base + (uint32_t)(ntp * 2048) + k3off); \
                _Pragma("unroll") for (int mt = 0; mt < MT; mt++) { \
                    mma_f(x + (mt * 8 + 2 * ntp) * 4,     af[mt], w0,  w1_); \
                    mma_f(x + (mt * 8 + 2 * ntp + 1) * 4, af[mt], w2_, w3_); } } } } while (0)

    #pragma unroll 1
    for (int s = 0; s < NSTEPS; s++) {
        const float tvalf = ((float)s + 0.5f) * dt;
        const uint32_t tval2 = pack_f16x2(tvalf, tvalf);

        // ======== GEMM1 (k-outer, f16 accum in hA) ========
        #pragma unroll
        for (int pair = 0; pair < 16; pair++) {
            const uint32_t biasA = hfma2(tval2, stw1p[pair * 8 + l4],     sb1p[pair * 8 + l4]);
            const uint32_t biasB = hfma2(tval2, stw1p[pair * 8 + 4 + l4], sb1p[pair * 8 + 4 + l4]);
            #pragma unroll
            for (int mt = 0; mt < MT; mt++) {
                uint32_t* h = hA + (pair * MT + mt) * 4;
                h[0] = biasA; h[1] = biasA; h[2] = biasB; h[3] = biasB;
            }
        }
        #pragma unroll
        for (int kt = 0; kt < 4; kt++) {
            uint32_t xk[MT * 4];
            #pragma unroll
            for (int mt = 0; mt < MT; mt++) {
                const float* xs = x + (mt * 8 + 2 * kt) * 4;
                xk[mt * 4 + 0] = pack_f16x2(xs[0], xs[1]);
                xk[mt * 4 + 1] = pack_f16x2(xs[2], xs[3]);
                xk[mt * 4 + 2] = pack_f16x2(xs[4], xs[5]);
                xk[mt * 4 + 3] = pack_f16x2(xs[6], xs[7]);
            }
            const uint32_t koff = KOFF(kt);
            #pragma unroll
            for (int pair = 0; pair < 16; pair++) {
                uint32_t w0, w1_, w2_, w3_;
                ldsm4(w0, w1_, w2_, w3_,
                      sbase + SM_W1 + (uint32_t)(pair * 2048) + ld_row + koff);
                #pragma unroll
                for (int mt = 0; mt < MT; mt++) {
                    mma_h(hA + (pair * MT + mt) * 4 + 0, xk + mt * 4, w0,  w1_);
                    mma_h(hA + (pair * MT + mt) * 4 + 2, xk + mt * 4, w2_, w3_);
                }
            }
        }

        // ==== GEMM2+GEMM3, chunk pipeline; hA silu FUSED into chunk 0's kt loop ====
        {
            uint32_t C2a[MT * 8], C2b[MT * 8];
            SILU_SLICE(0);                       // prime slice 0
            G2_INIT(0, C2a); G2_MMA(0, C2a, 1);  // silu slice kt+1 under mma kt
            #pragma unroll
            for (int ch = 0; ch < 8; ch += 2) {
                G2_INIT(ch + 1, C2b); G2_MMA(ch + 1, C2b, 0);
                EPI_G3(ch, C2a);
                if (ch < 6) { G2_INIT(ch + 2, C2a); G2_MMA(ch + 2, C2a, 0); }
                EPI_G3(ch + 1, C2b);
            }
        }

        // ---- x += dt * b3 ----
        #pragma unroll
        for (int nt = 0; nt < 8; nt++) {
            float2 p = *(const float2*)(sdb3 + nt * 8 + q2);
            #pragma unroll
            for (int mt = 0; mt < MT; mt++) {
                float* xs = x + (mt * 8 + nt) * 4;
                xs[0] += p.x; xs[1] += p.y; xs[2] += p.x; xs[3] += p.y;
            }
        }
    }

    // ---- store result ----
    #pragma unroll
    for (int mt = 0; mt < MT; mt++) {
        float* pA = out + (rowBase + mt * 16) * DIMX;
        float* pB = out + (rowBase + mt * 16 + 8) * DIMX;
        #pragma unroll
        for (int nt = 0; nt < 8; nt++) {
            const float* xs = x + (mt * 8 + nt) * 4;
            *(float2*)(pA + nt * 8 + q2) = make_float2(xs[0], xs[1]);
            *(float2*)(pB + nt * 8 + q2) = make_float2(xs[2], xs[3]);
        }
    }
    #undef KOFF
    #undef SILU_SLICE
    #undef G2_INIT
    #undef G2_MMA
    #undef EPI_G3
}

// ======================= kernel ==================================
__global__ void __launch_bounds__(NTHREADS, 1) flow_kernel(
    const float* __restrict__ x0, const float* __restrict__ W1,
    const float* __restrict__ b1, const float* __restrict__ W2,
    const float* __restrict__ b2, const float* __restrict__ W3,
    const float* __restrict__ b3, float* __restrict__ out)
{
    extern __shared__ char smem[];
    const uint32_t sbase = smem_to_u32(smem);
    const int tid = threadIdx.x;

    uint32_t* sb1p  = (uint32_t*)(smem + SM_B1P);
    uint32_t* stw1p = (uint32_t*)(smem + SM_TW1P);
    uint32_t* sb2p  = (uint32_t*)(smem + SM_B2P);
    float*    sdb3  = (float*)(smem + SM_DB3);

    const float dt = 1.0f / NSTEPS;

    if (tid < 128) {
        sb1p[tid]  = pack_f16x2(b1[2 * tid], b1[2 * tid + 1]);
        stw1p[tid] = pack_f16x2(W1[DIMX * HIDX + 2 * tid], W1[DIMX * HIDX + 2 * tid + 1]);
        sb2p[tid]  = pack_f16x2(b2[2 * tid], b2[2 * tid + 1]);
    }
    if (tid < DIMX) sdb3[tid] = dt * b3[tid];

    for (int idx = tid; idx < DIMX * HIDX; idx += NTHREADS) {          // W1 (64k,256n)
        int k = idx >> 8, n = idx & 255;
        uint32_t off = (uint32_t)(n * 128 + k * 2);
        *(__half*)(smem + SM_W1 + SWZ(off)) = __float2half(W1[idx]);
    }
    for (int idx = tid; idx < HIDX * HIDX; idx += NTHREADS) {          // W2 (256k,256n)
        int k = idx >> 8, n = idx & 255;
        int c = k >> 6, kk = k & 63;
        uint32_t off = (uint32_t)(n * 128 + kk * 2);
        *(__half*)(smem + SM_W2 + c * 32768 + SWZ(off)) = __float2half(W2[idx]);
    }
    for (int idx = tid; idx < HIDX * DIMX; idx += NTHREADS) {          // W3 (256k,64n), x dt
        int k = idx >> 6, n = idx & 63;
        int c = k >> 6, kk = k & 63;
        uint32_t off = (uint32_t)(n * 128 + kk * 2);
        *(__half*)(smem + SM_W3 + c * 8192 + SWZ(off)) = __float2half(dt * W3[idx]);
    }
    __syncthreads();

    if (blockIdx.x < NBIG) {
        flow_body<2>((long)blockIdx.x * 256, x0, out, sbase, sb1p, stw1p, sb2p, sdb3);
    } else {
        flow_body<1>((long)BIGROWS + (long)(blockIdx.x - NBIG) * 128,
                     x0, out, sbase, sb1p, stw1p, sb2p, sdb3);
    }
}

// ======================= launch ==================================
extern "C" void kernel_launch(void* const* d_in, const int* in_sizes, int n_in,
                              void* d_out, int out_size) {
    const float* x0 = (const float*)d_in[0];
    const float* W1 = (const float*)d_in[1];
    const float* b1 = (const float*)d_in[2];
    const float* W2 = (const float*)d_in[3];
    const float* b2 = (const float*)d_in[4];
    const float* W3 = (const float*)d_in[5];
    const float* b3 = (const float*)d_in[6];
    float* out = (float*)d_out;

    cudaFuncSetAttribute(flow_kernel, cudaFuncAttributeMaxDynamicSharedMemorySize, SMEM_BYTES);
    flow_kernel<<<NBIG + NSMALL, NTHREADS, SMEM_BYTES>>>(x0, W1, b1, W2, b2, W3, b3, out);
}